// round 1
// baseline (speedup 1.0000x reference)
#include <cuda_runtime.h>
#include <cuda_bf16.h>

// Problem constants
#define Bn 16
#define Fc 64
#define Ec 16
#define Hh 64
#define Ww 64
#define HW (Hh * Ww)

// Scratch (device globals: allocation-free rule)
__device__ float g_x[Bn * Fc * HW];            // relu(conv1(state))  ~16.8MB
__device__ float g_partials[Bn * 32 * 16 * 64]; // per-chunk partial sums ~2MB

// ---------------------------------------------------------------------------
// 3x3 'same' conv, CI=64, CO = co_total (multiple of 16), stride 1.
// Grid: B * 8 ytiles * (co_total/16). Block: 256 threads.
// Each block: 8 rows x 64 cols x 16 output channels. 2 pixels/thread.
// ACT: 0 = relu, 1 = sigmoid.
// ---------------------------------------------------------------------------
#define CIC 8

template <int ACT>
__global__ __launch_bounds__(256) void conv3x3_kernel(
    const float* __restrict__ in, const float* __restrict__ w,
    const float* __restrict__ bias, float* __restrict__ out, int co_total)
{
    const int ngroups = co_total >> 4;
    const int bi = blockIdx.x;
    const int cog = bi % ngroups;
    const int ytile = (bi / ngroups) & 7;
    const int b = bi / (ngroups * 8);
    const int co_base = cog << 4;

    __shared__ float s_in[CIC * 10 * 66];   // [ci][row(10)][col(66)]  21.1KB
    __shared__ float s_w[CIC * 9 * 16];     // [ci][tap][co16]          4.6KB

    const int tid = threadIdx.x;
    const int row0 = tid >> 6;      // 0..3
    const int col = tid & 63;
    const int row1 = row0 + 4;

    float acc0[16], acc1[16];
#pragma unroll
    for (int j = 0; j < 16; j++) { acc0[j] = 0.f; acc1[j] = 0.f; }

    const float* in_b = in + (long)b * (Fc * HW);

    for (int cic = 0; cic < Fc; cic += CIC) {
        __syncthreads();
        // input tile: rows ytile*8-1 .. ytile*8+8, cols -1..64 (zero border)
        for (int idx = tid; idx < CIC * 10 * 66; idx += 256) {
            int ci = idx / 660;
            int rem = idx - ci * 660;
            int r = rem / 66;
            int c = rem - r * 66;
            int gy = ytile * 8 + r - 1;
            int gx = c - 1;
            float v = 0.f;
            if (gy >= 0 && gy < Hh && gx >= 0 && gx < Ww)
                v = in_b[(cic + ci) * HW + gy * Ww + gx];
            s_in[idx] = v;
        }
        // weights transposed: s_w[(ci*9+tap)*16 + co] = w[(co_base+co)*CI*9 + (cic+ci)*9 + tap]
        for (int idx = tid; idx < CIC * 9 * 16; idx += 256) {
            int co = idx & 15;
            int rest = idx >> 4;
            int tap = rest % 9;
            int ci = rest / 9;
            s_w[idx] = w[(co_base + co) * (Fc * 9) + (cic + ci) * 9 + tap];
        }
        __syncthreads();

        for (int ci = 0; ci < CIC; ci++) {
            const float* sp = s_in + ci * 660;
#pragma unroll
            for (int tap = 0; tap < 9; tap++) {
                const int dy = tap / 3, dx = tap % 3;
                float i0 = sp[(row0 + dy) * 66 + col + dx];
                float i1 = sp[(row1 + dy) * 66 + col + dx];
                const float4* wp = (const float4*)(s_w + (ci * 9 + tap) * 16);
#pragma unroll
                for (int q = 0; q < 4; q++) {
                    float4 wv = wp[q];
                    acc0[q * 4 + 0] = fmaf(i0, wv.x, acc0[q * 4 + 0]);
                    acc1[q * 4 + 0] = fmaf(i1, wv.x, acc1[q * 4 + 0]);
                    acc0[q * 4 + 1] = fmaf(i0, wv.y, acc0[q * 4 + 1]);
                    acc1[q * 4 + 1] = fmaf(i1, wv.y, acc1[q * 4 + 1]);
                    acc0[q * 4 + 2] = fmaf(i0, wv.z, acc0[q * 4 + 2]);
                    acc1[q * 4 + 2] = fmaf(i1, wv.z, acc1[q * 4 + 2]);
                    acc0[q * 4 + 3] = fmaf(i0, wv.w, acc0[q * 4 + 3]);
                    acc1[q * 4 + 3] = fmaf(i1, wv.w, acc1[q * 4 + 3]);
                }
            }
        }
    }

    const int y0 = ytile * 8 + row0;
    const int y1 = y0 + 4;
#pragma unroll
    for (int j = 0; j < 16; j++) {
        float bj = bias[co_base + j];
        float v0 = acc0[j] + bj;
        float v1 = acc1[j] + bj;
        if (ACT == 0) {
            v0 = fmaxf(v0, 0.f);
            v1 = fmaxf(v1, 0.f);
        } else {
            v0 = 1.f / (1.f + __expf(-v0));
            v1 = 1.f / (1.f + __expf(-v1));
        }
        float* ob = out + ((long)b * co_total + co_base + j) * HW;
        ob[y0 * Ww + col] = v0;
        ob[y1 * Ww + col] = v1;
    }
}

// ---------------------------------------------------------------------------
// Fused: cs[b,o,p] = sum_f c3_w[o,f]*state[b,f,p] (chunk of 128 pixels, smem),
// then partial[b,chunk,e,o] = sum_p relu(attn[b,e,p]*cs[b,o,p] + c3_b[o]).
// Grid: B*32. Block: 256 threads. Dynamic smem 59392B.
// ---------------------------------------------------------------------------
#define FUSE_SMEM_FLOATS (64 * 64 + 16 * 128 + 128 * 68)
#define FUSE_SMEM_BYTES (FUSE_SMEM_FLOATS * 4)

__global__ __launch_bounds__(256) void fuse_kernel(
    const float* __restrict__ state, const float* __restrict__ attn,
    const float* __restrict__ c3_w, const float* __restrict__ c3_b)
{
    extern __shared__ float smem[];
    float* w_t = smem;               // [f][o]        4096
    float* attn_s = smem + 4096;     // [e][pp]       2048
    float* cs_s = smem + 6144;       // [pp][o pad68] 8704

    const int b = blockIdx.x >> 5;
    const int chunk = blockIdx.x & 31;
    const int pbase = chunk * 128;
    const int tid = threadIdx.x;

    // load c3_w transposed: read coalesced [o][f], write [f][o]
#pragma unroll
    for (int k = 0; k < 16; k++) {
        int idx = tid + k * 256;
        float v = c3_w[idx];
        int o = idx >> 6, f = idx & 63;
        w_t[f * 64 + o] = v;
    }
    // load attn chunk
#pragma unroll
    for (int k = 0; k < 8; k++) {
        int idx = tid + k * 256;
        int e = idx >> 7, pp = idx & 127;
        attn_s[idx] = attn[((long)b * 16 + e) * HW + pbase + pp];
    }
    __syncthreads();

    // cs chunk: thread (pp, oh) computes 32 o's for one pixel
    {
        const int pp = tid & 127;
        const int oh = tid >> 7;  // 0/1
        float c[32];
#pragma unroll
        for (int j = 0; j < 32; j++) c[j] = 0.f;
        const float* sb = state + (long)b * (Fc * HW) + pbase + pp;
#pragma unroll 4
        for (int f = 0; f < Fc; f++) {
            float s = sb[f * HW];
            const float4* wp = (const float4*)(w_t + f * 64 + oh * 32);
#pragma unroll
            for (int q = 0; q < 8; q++) {
                float4 wv = wp[q];
                c[q * 4 + 0] = fmaf(s, wv.x, c[q * 4 + 0]);
                c[q * 4 + 1] = fmaf(s, wv.y, c[q * 4 + 1]);
                c[q * 4 + 2] = fmaf(s, wv.z, c[q * 4 + 2]);
                c[q * 4 + 3] = fmaf(s, wv.w, c[q * 4 + 3]);
            }
        }
        float4* cp = (float4*)(cs_s + pp * 68 + oh * 32);
#pragma unroll
        for (int q = 0; q < 8; q++)
            cp[q] = make_float4(c[q * 4], c[q * 4 + 1], c[q * 4 + 2], c[q * 4 + 3]);
    }
    __syncthreads();

    // reduction: thread (e, oq) accumulates 4 o's over 128 pixels
    {
        const int e = tid >> 4;
        const int oq = tid & 15;
        const float4 bias = ((const float4*)c3_b)[oq];
        float4 acc = make_float4(0.f, 0.f, 0.f, 0.f);
        const float* arow = attn_s + e * 128;
#pragma unroll 4
        for (int pp = 0; pp < 128; pp++) {
            float a = arow[pp];
            float4 cv = *(const float4*)(cs_s + pp * 68 + oq * 4);
            acc.x += fmaxf(fmaf(a, cv.x, bias.x), 0.f);
            acc.y += fmaxf(fmaf(a, cv.y, bias.y), 0.f);
            acc.z += fmaxf(fmaf(a, cv.z, bias.z), 0.f);
            acc.w += fmaxf(fmaf(a, cv.w, bias.w), 0.f);
        }
        float4* po = (float4*)(g_partials + ((long)(b * 32 + chunk)) * 1024 + e * 64 + oq * 4);
        *po = acc;
    }
}

// ---------------------------------------------------------------------------
// Final reduce: out[b,e,o] = (260*relu(c3_b[o]) + sum_chunks partial) / 4356
// ---------------------------------------------------------------------------
__global__ __launch_bounds__(256) void reduce_kernel(
    const float* __restrict__ c3_b, float* __restrict__ out)
{
    int gid = blockIdx.x * 256 + threadIdx.x;  // 0..16383
    int b = gid >> 10;
    int eo = gid & 1023;
    int o = gid & 63;
    float sum = 260.f * fmaxf(c3_b[o], 0.f);
    const float* p = g_partials + (long)b * 32 * 1024 + eo;
#pragma unroll
    for (int c = 0; c < 32; c++) sum += p[c * 1024];
    out[gid] = sum * (1.f / 4356.f);
}

// ---------------------------------------------------------------------------
extern "C" void kernel_launch(void* const* d_in, const int* in_sizes, int n_in,
                              void* d_out, int out_size)
{
    const float* state = (const float*)d_in[0];
    const float* pre_w = (const float*)d_in[1];
    const float* pre_b = (const float*)d_in[2];
    const float* attn_w = (const float*)d_in[3];
    const float* attn_b = (const float*)d_in[4];
    const float* c3_w = (const float*)d_in[5];
    const float* c3_b = (const float*)d_in[6];

    float* out = (float*)d_out;                 // (B,E,F) = 16384 floats
    float* attn = out + Bn * Ec * Fc;           // (B,E,H,W) = 1048576 floats

    void* p_x = nullptr;
    cudaGetSymbolAddress(&p_x, g_x);
    float* xbuf = (float*)p_x;

    cudaFuncSetAttribute(fuse_kernel, cudaFuncAttributeMaxDynamicSharedMemorySize,
                         FUSE_SMEM_BYTES);

    // conv1: state -> x (relu), CO=64
    conv3x3_kernel<0><<<Bn * 8 * 4, 256>>>(state, pre_w, pre_b, xbuf, 64);
    // conv2: x -> attn (sigmoid), CO=16, written directly into d_out
    conv3x3_kernel<1><<<Bn * 8 * 1, 256>>>(xbuf, attn_w, attn_b, attn, 16);
    // fused cs-GEMM + relu-reduction partials
    fuse_kernel<<<Bn * 32, 256, FUSE_SMEM_BYTES>>>(state, attn, c3_w, c3_b);
    // final reduce + pad term
    reduce_kernel<<<64, 256>>>(c3_b, out);
}

// round 2
// speedup vs baseline: 1.0284x; 1.0284x over previous
#include <cuda_runtime.h>
#include <cuda_bf16.h>

// Problem constants
#define Bn 16
#define Fc 64
#define Ec 16
#define Hh 64
#define Ww 64
#define HW (Hh * Ww)

// Scratch (device globals: allocation-free rule)
__device__ float g_x[Bn * Fc * HW];             // relu(conv1(state))  ~16.8MB
__device__ float g_partials[Bn * 32 * 16 * 64]; // per-chunk partial sums ~2MB

// ---------------------------------------------------------------------------
// Packed fp32x2 helpers (sm_103a FFMA2 — ptxas never auto-fuses this)
// ---------------------------------------------------------------------------
__device__ __forceinline__ unsigned long long f32x2_fma(
    unsigned long long a, unsigned long long b, unsigned long long c)
{
    unsigned long long d;
    asm("fma.rn.f32x2 %0, %1, %2, %3;" : "=l"(d) : "l"(a), "l"(b), "l"(c));
    return d;
}
__device__ __forceinline__ unsigned long long f32x2_pack(float lo, float hi)
{
    unsigned long long d;
    asm("mov.b64 %0, {%1, %2};" : "=l"(d) : "f"(lo), "f"(hi));
    return d;
}
__device__ __forceinline__ float2 f32x2_unpack(unsigned long long v)
{
    float2 r;
    asm("mov.b64 {%0, %1}, %2;" : "=f"(r.x), "=f"(r.y) : "l"(v));
    return r;
}

// ---------------------------------------------------------------------------
// 3x3 'same' conv, CI=64, CO = co_total (multiple of 16), stride 1.
// Tile: (NPIX*4) rows x 64 cols x 16 output channels per block, 256 threads,
// NPIX pixels per thread packed as NPIX/2 f32x2 pairs.
// ACT: 0 = relu, 1 = sigmoid.
// ---------------------------------------------------------------------------
#define CIC 8

template <int ACT, int NPIX>
__global__ __launch_bounds__(256) void conv3x3_kernel(
    const float* __restrict__ in, const float* __restrict__ w,
    const float* __restrict__ bias, float* __restrict__ out, int co_total)
{
    constexpr int ROWS = NPIX * 4;
    constexpr int YT = 64 / ROWS;
    constexpr int NPAIR = NPIX / 2;
    constexpr int INROWS = ROWS + 2;

    const int ngroups = co_total >> 4;
    const int bi = blockIdx.x;
    const int cog = bi % ngroups;
    const int ytile = (bi / ngroups) % YT;
    const int b = bi / (ngroups * YT);
    const int co_base = cog << 4;

    __shared__ float s_in[CIC * INROWS * 66];          // input tile
    __shared__ unsigned long long s_w2[CIC * 9 * 16];  // weights, duplicated halves

    const int tid = threadIdx.x;
    const int row0 = tid >> 6;      // 0..3
    const int col = tid & 63;

    unsigned long long acc2[NPAIR * 16];
#pragma unroll
    for (int j = 0; j < NPAIR * 16; j++) acc2[j] = 0ull;

    const float* in_b = in + (long)b * (Fc * HW);

    for (int cic = 0; cic < Fc; cic += CIC) {
        __syncthreads();
        // input tile: rows ytile*ROWS-1 .. +ROWS, cols -1..64 (zero border)
        for (int idx = tid; idx < CIC * INROWS * 66; idx += 256) {
            int ci = idx / (INROWS * 66);
            int rem = idx - ci * (INROWS * 66);
            int r = rem / 66;
            int c = rem - r * 66;
            int gy = ytile * ROWS + r - 1;
            int gx = c - 1;
            float v = 0.f;
            if (gy >= 0 && gy < Hh && gx >= 0 && gx < Ww)
                v = in_b[(cic + ci) * HW + gy * Ww + gx];
            s_in[idx] = v;
        }
        // weights, both halves duplicated for f32x2
        for (int idx = tid; idx < CIC * 9 * 16; idx += 256) {
            int co = idx & 15;
            int rest = idx >> 4;
            int tap = rest % 9;
            int ci = rest / 9;
            float wv = w[(co_base + co) * (Fc * 9) + (cic + ci) * 9 + tap];
            s_w2[idx] = f32x2_pack(wv, wv);
        }
        __syncthreads();

        for (int ci = 0; ci < CIC; ci++) {
            const float* sp = s_in + ci * (INROWS * 66);
#pragma unroll
            for (int tap = 0; tap < 9; tap++) {
                const int dy = tap / 3, dx = tap % 3;
                unsigned long long a[NPAIR];
#pragma unroll
                for (int k = 0; k < NPAIR; k++) {
                    float ilo = sp[(row0 + 8 * k + dy) * 66 + col + dx];
                    float ihi = sp[(row0 + 8 * k + 4 + dy) * 66 + col + dx];
                    a[k] = f32x2_pack(ilo, ihi);
                }
                const ulonglong2* wp = (const ulonglong2*)(s_w2 + (ci * 9 + tap) * 16);
#pragma unroll
                for (int q = 0; q < 8; q++) {
                    ulonglong2 wv = wp[q];
#pragma unroll
                    for (int k = 0; k < NPAIR; k++) {
                        acc2[k * 16 + q * 2 + 0] = f32x2_fma(a[k], wv.x, acc2[k * 16 + q * 2 + 0]);
                        acc2[k * 16 + q * 2 + 1] = f32x2_fma(a[k], wv.y, acc2[k * 16 + q * 2 + 1]);
                    }
                }
            }
        }
    }

#pragma unroll
    for (int j = 0; j < 16; j++) {
        float bj = bias[co_base + j];
        float* ob = out + ((long)b * co_total + co_base + j) * HW;
#pragma unroll
        for (int k = 0; k < NPAIR; k++) {
            float2 v = f32x2_unpack(acc2[k * 16 + j]);
            v.x += bj;
            v.y += bj;
            if (ACT == 0) {
                v.x = fmaxf(v.x, 0.f);
                v.y = fmaxf(v.y, 0.f);
            } else {
                v.x = 1.f / (1.f + __expf(-v.x));
                v.y = 1.f / (1.f + __expf(-v.y));
            }
            int y_lo = ytile * ROWS + row0 + 8 * k;
            ob[y_lo * Ww + col] = v.x;
            ob[(y_lo + 4) * Ww + col] = v.y;
        }
    }
}

// ---------------------------------------------------------------------------
// Fused: cs[b,o,p] = sum_f c3_w[o,f]*state[b,f,p] (chunk of 128 pixels, smem),
// then partial[b,chunk,e,o] = sum_p relu(attn[b,e,p]*cs[b,o,p] + c3_b[o]).
// Grid: B*32. Block: 256 threads. Dynamic smem 59392B.
// ---------------------------------------------------------------------------
#define FUSE_SMEM_FLOATS (64 * 64 + 16 * 128 + 128 * 68)
#define FUSE_SMEM_BYTES (FUSE_SMEM_FLOATS * 4)

__global__ __launch_bounds__(256) void fuse_kernel(
    const float* __restrict__ state, const float* __restrict__ attn,
    const float* __restrict__ c3_w, const float* __restrict__ c3_b)
{
    extern __shared__ float smem[];
    float* w_t = smem;               // [f][o]        4096
    float* attn_s = smem + 4096;     // [e][pp]       2048
    float* cs_s = smem + 6144;       // [pp][o pad68] 8704

    const int b = blockIdx.x >> 5;
    const int chunk = blockIdx.x & 31;
    const int pbase = chunk * 128;
    const int tid = threadIdx.x;

    // load c3_w transposed: read coalesced [o][f], write [f][o]
#pragma unroll
    for (int k = 0; k < 16; k++) {
        int idx = tid + k * 256;
        float v = c3_w[idx];
        int o = idx >> 6, f = idx & 63;
        w_t[f * 64 + o] = v;
    }
    // load attn chunk
#pragma unroll
    for (int k = 0; k < 8; k++) {
        int idx = tid + k * 256;
        int e = idx >> 7, pp = idx & 127;
        attn_s[idx] = attn[((long)b * 16 + e) * HW + pbase + pp];
    }
    __syncthreads();

    // cs chunk: thread (pp, oh) computes 32 o's (16 f32x2 pairs) for one pixel
    {
        const int pp = tid & 127;
        const int oh = tid >> 7;  // 0/1
        unsigned long long c2[16];
#pragma unroll
        for (int j = 0; j < 16; j++) c2[j] = 0ull;
        const float* sb = state + (long)b * (Fc * HW) + pbase + pp;
#pragma unroll 4
        for (int f = 0; f < Fc; f++) {
            float s = sb[f * HW];
            unsigned long long a = f32x2_pack(s, s);
            const ulonglong2* wp = (const ulonglong2*)(w_t + f * 64 + oh * 32);
#pragma unroll
            for (int q = 0; q < 8; q++) {
                ulonglong2 wv = wp[q];
                c2[q * 2 + 0] = f32x2_fma(a, wv.x, c2[q * 2 + 0]);
                c2[q * 2 + 1] = f32x2_fma(a, wv.y, c2[q * 2 + 1]);
            }
        }
        unsigned long long* cp = (unsigned long long*)(cs_s + pp * 68 + oh * 32);
#pragma unroll
        for (int j = 0; j < 16; j++) cp[j] = c2[j];
    }
    __syncthreads();

    // reduction: thread (e, oq) accumulates 4 o's over 128 pixels
    {
        const int e = tid >> 4;
        const int oq = tid & 15;
        const float4 bias = ((const float4*)c3_b)[oq];
        float4 acc = make_float4(0.f, 0.f, 0.f, 0.f);
        const float* arow = attn_s + e * 128;
#pragma unroll 4
        for (int pp = 0; pp < 128; pp++) {
            float a = arow[pp];
            float4 cv = *(const float4*)(cs_s + pp * 68 + oq * 4);
            acc.x += fmaxf(fmaf(a, cv.x, bias.x), 0.f);
            acc.y += fmaxf(fmaf(a, cv.y, bias.y), 0.f);
            acc.z += fmaxf(fmaf(a, cv.z, bias.z), 0.f);
            acc.w += fmaxf(fmaf(a, cv.w, bias.w), 0.f);
        }
        float4* po = (float4*)(g_partials + ((long)(b * 32 + chunk)) * 1024 + e * 64 + oq * 4);
        *po = acc;
    }
}

// ---------------------------------------------------------------------------
// Final reduce: out[b,e,o] = (260*relu(c3_b[o]) + sum_chunks partial) / 4356
// ---------------------------------------------------------------------------
__global__ __launch_bounds__(256) void reduce_kernel(
    const float* __restrict__ c3_b, float* __restrict__ out)
{
    int gid = blockIdx.x * 256 + threadIdx.x;  // 0..16383
    int o = gid & 63;
    float sum = 260.f * fmaxf(c3_b[o], 0.f);
    int b = gid >> 10;
    int eo = gid & 1023;
    const float* p = g_partials + (long)b * 32 * 1024 + eo;
#pragma unroll
    for (int c = 0; c < 32; c++) sum += p[c * 1024];
    out[gid] = sum * (1.f / 4356.f);
}

// ---------------------------------------------------------------------------
extern "C" void kernel_launch(void* const* d_in, const int* in_sizes, int n_in,
                              void* d_out, int out_size)
{
    const float* state = (const float*)d_in[0];
    const float* pre_w = (const float*)d_in[1];
    const float* pre_b = (const float*)d_in[2];
    const float* attn_w = (const float*)d_in[3];
    const float* attn_b = (const float*)d_in[4];
    const float* c3_w = (const float*)d_in[5];
    const float* c3_b = (const float*)d_in[6];

    float* out = (float*)d_out;                 // (B,E,F) = 16384 floats
    float* attn = out + Bn * Ec * Fc;           // (B,E,H,W) = 1048576 floats

    void* p_x = nullptr;
    cudaGetSymbolAddress(&p_x, g_x);
    float* xbuf = (float*)p_x;

    cudaFuncSetAttribute(fuse_kernel, cudaFuncAttributeMaxDynamicSharedMemorySize,
                         FUSE_SMEM_BYTES);

    // conv1: state -> x (relu), CO=64, 16-row tiles, 4 px/thread
    conv3x3_kernel<0, 4><<<Bn * 4 * 4, 256>>>(state, pre_w, pre_b, xbuf, 64);
    // conv2: x -> attn (sigmoid), CO=16, 8-row tiles, 2 px/thread
    conv3x3_kernel<1, 2><<<Bn * 8 * 1, 256>>>(xbuf, attn_w, attn_b, attn, 16);
    // fused cs-GEMM + relu-reduction partials
    fuse_kernel<<<Bn * 32, 256, FUSE_SMEM_BYTES>>>(state, attn, c3_w, c3_b);
    // final reduce + pad term
    reduce_kernel<<<64, 256>>>(c3_b, out);
}

// round 4
// speedup vs baseline: 1.3400x; 1.3030x over previous
#include <cuda_runtime.h>
#include <cuda_bf16.h>
#include <cstdint>

// Problem constants
#define Bn 16
#define Fc 64
#define Ec 16
#define Hh 64
#define Ww 64
#define HW (Hh * Ww)

// Scratch (device globals: allocation-free rule)
__device__ float g_x[Bn * Fc * HW];               // relu(conv1(state)) fp32 NCHW
__device__ float g_partials[Bn * 32 * 16 * 64];   // fuse partial sums
__device__ __align__(16) uint32_t g_xhi[Bn * HW * 32];  // state bf16-hi, [b][pix][ci-pair]
__device__ __align__(16) uint32_t g_xlo[Bn * HW * 32];  // state bf16-lo
__device__ __align__(16) uint8_t  g_wtile[9 * 16384];   // W tiles [tap][hi|lo][co][ci] bf16

// ---------------------------------------------------------------------------
// mma.sync m16n8k16 row.col f32.bf16.bf16.f32 (baseline PTX, OK at compute_103)
// ---------------------------------------------------------------------------
__device__ __forceinline__ void mma16816(float* d, const uint32_t* a, const uint32_t* b)
{
    asm volatile(
        "mma.sync.aligned.m16n8k16.row.col.f32.bf16.bf16.f32 "
        "{%0,%1,%2,%3}, {%4,%5,%6,%7}, {%8,%9}, {%0,%1,%2,%3};"
        : "+f"(d[0]), "+f"(d[1]), "+f"(d[2]), "+f"(d[3])
        : "r"(a[0]), "r"(a[1]), "r"(a[2]), "r"(a[3]), "r"(b[0]), "r"(b[1]));
}

// ---------------------------------------------------------------------------
// Prep: weights -> bf16 hi/lo tiles per tap, layout [tap][part][co][ci]
// ---------------------------------------------------------------------------
__global__ __launch_bounds__(256) void wprep_kernel(const float* __restrict__ w)
{
    int idx = blockIdx.x * 256 + threadIdx.x;  // 0..18431 = (tap, co, ci-pair)
    int tap = idx >> 11;
    int rem = idx & 2047;
    int co = rem >> 5, ci2 = rem & 31;
    float v0 = w[(co * 64 + 2 * ci2) * 9 + tap];
    float v1 = w[(co * 64 + 2 * ci2 + 1) * 9 + tap];
    __nv_bfloat16 h0 = __float2bfloat16(v0);
    __nv_bfloat16 h1 = __float2bfloat16(v1);
    __nv_bfloat16 l0 = __float2bfloat16(v0 - __bfloat162float(h0));
    __nv_bfloat16 l1 = __float2bfloat16(v1 - __bfloat162float(h1));
    uint32_t hp = ((uint32_t)__bfloat16_as_ushort(h1) << 16) | __bfloat16_as_ushort(h0);
    uint32_t lp = ((uint32_t)__bfloat16_as_ushort(l1) << 16) | __bfloat16_as_ushort(l0);
    *(uint32_t*)(g_wtile + tap * 16384 + co * 128 + ci2 * 4) = hp;
    *(uint32_t*)(g_wtile + tap * 16384 + 8192 + co * 128 + ci2 * 4) = lp;
}

// ---------------------------------------------------------------------------
// Prep: state NCHW fp32 -> [b][pix][ci] bf16 hi/lo (pixel-major, 128B/pixel)
// ---------------------------------------------------------------------------
__global__ __launch_bounds__(256) void xprep_kernel(const float* __restrict__ state)
{
    __shared__ float s[64 * 65];
    int b = blockIdx.x >> 6, y = blockIdx.x & 63;
    int tid = threadIdx.x;
#pragma unroll
    for (int k = 0; k < 16; k++) {
        int idx = tid + k * 256;
        int ci = idx >> 6, x = idx & 63;
        s[ci * 65 + x] = state[((long)(b * 64 + ci) * 64 + y) * 64 + x];
    }
    __syncthreads();
#pragma unroll
    for (int k = 0; k < 8; k++) {
        int idx = tid + k * 256;
        int x = idx >> 5, j = idx & 31;
        float v0 = s[(2 * j) * 65 + x];
        float v1 = s[(2 * j + 1) * 65 + x];
        __nv_bfloat16 h0 = __float2bfloat16(v0);
        __nv_bfloat16 h1 = __float2bfloat16(v1);
        __nv_bfloat16 l0 = __float2bfloat16(v0 - __bfloat162float(h0));
        __nv_bfloat16 l1 = __float2bfloat16(v1 - __bfloat162float(h1));
        long o = ((long)b * 4096 + y * 64 + x) * 32 + j;
        g_xhi[o] = ((uint32_t)__bfloat16_as_ushort(h1) << 16) | __bfloat16_as_ushort(h0);
        g_xlo[o] = ((uint32_t)__bfloat16_as_ushort(l1) << 16) | __bfloat16_as_ushort(l0);
    }
}

// ---------------------------------------------------------------------------
// conv1 via mma.sync: block = (b, 2-row strip) -> D[128 pix][64 co].
// 9 taps x 4 k16-steps x 3 hi/lo products accumulated in registers.
// smem tiles with 144B row pitch (2-way max bank conflict on frag loads).
// ---------------------------------------------------------------------------
#define APITCH 144
#define AH_OFF 0
#define AL_OFF (128 * APITCH)                 /* 18432 */
#define BH_OFF (2 * 128 * APITCH)             /* 36864 */
#define BL_OFF (BH_OFF + 64 * APITCH)         /* 46080 */
#define BIAS_OFF (BL_OFF + 64 * APITCH)       /* 55296 */
#define CONV1_SMEM (BIAS_OFF + 256)           /* 55552 */

__global__ __launch_bounds__(128) void conv1_mma_kernel(const float* __restrict__ bias)
{
    extern __shared__ char smem[];
    const int tid = threadIdx.x;
    const int w = tid >> 5;
    const int l = tid & 31;
    const int b = blockIdx.x >> 5;
    const int y0 = (blockIdx.x & 31) * 2;

    if (tid < 64) *(float*)(smem + BIAS_OFF + tid * 4) = bias[tid];

    float d[2][8][4];
#pragma unroll
    for (int mt = 0; mt < 2; mt++)
#pragma unroll
        for (int nb = 0; nb < 8; nb++)
#pragma unroll
            for (int j = 0; j < 4; j++) d[mt][nb][j] = 0.f;

    const uint4* xh4 = (const uint4*)g_xhi;
    const uint4* xl4 = (const uint4*)g_xlo;

    for (int tap = 0; tap < 9; tap++) {
        const int dy = tap / 3 - 1;
        const int dx = tap % 3 - 1;
        if (tap) __syncthreads();

        // stage A: thread = pixel row m (0..127); 128B of ci hi/lo per pixel
        {
            const int y = y0 + (tid >> 6) + dy;
            const int xx = (tid & 63) + dx;
            const bool ok = ((unsigned)y < 64u) && ((unsigned)xx < 64u);
            const long pix8 = ((long)b * 4096 + y * 64 + xx) * 8;
            char* arh = smem + AH_OFF + tid * APITCH;
            char* arl = smem + AL_OFF + tid * APITCH;
#pragma unroll
            for (int q = 0; q < 8; q++) {
                uint4 vh = make_uint4(0, 0, 0, 0), vl = make_uint4(0, 0, 0, 0);
                if (ok) { vh = xh4[pix8 + q]; vl = xl4[pix8 + q]; }
                *(uint4*)(arh + q * 16) = vh;
                *(uint4*)(arl + q * 16) = vl;
            }
        }
        // stage B: [co][ci] rows, hi then lo (each 64 rows x 128B = 512 uint4)
        {
            const uint4* wsrc = (const uint4*)(g_wtile + tap * 16384);
#pragma unroll
            for (int i = 0; i < 4; i++) {
                int idx = tid + i * 128;
                int row = idx >> 3, c = idx & 7;
                *(uint4*)(smem + BH_OFF + row * APITCH + c * 16) = wsrc[idx];
            }
#pragma unroll
            for (int i = 0; i < 4; i++) {
                int idx = tid + i * 128;
                int row = idx >> 3, c = idx & 7;
                *(uint4*)(smem + BL_OFF + row * APITCH + c * 16) = wsrc[512 + idx];
            }
        }
        __syncthreads();

        const int lr = l >> 2;          // 0..7
        const int lk = (l & 3) * 4;     // k-pair byte offset within 32B k16 chunk
#pragma unroll
        for (int kb = 0; kb < 4; kb++) {
            uint32_t ah[2][4], al[2][4];
#pragma unroll
            for (int mt = 0; mt < 2; mt++) {
                const char* ar = smem + AH_OFF + (w * 32 + mt * 16 + lr) * APITCH + kb * 32 + lk;
                ah[mt][0] = *(const uint32_t*)ar;
                ah[mt][1] = *(const uint32_t*)(ar + 8 * APITCH);
                ah[mt][2] = *(const uint32_t*)(ar + 16);
                ah[mt][3] = *(const uint32_t*)(ar + 8 * APITCH + 16);
                const char* al_p = ar + (AL_OFF - AH_OFF);
                al[mt][0] = *(const uint32_t*)al_p;
                al[mt][1] = *(const uint32_t*)(al_p + 8 * APITCH);
                al[mt][2] = *(const uint32_t*)(al_p + 16);
                al[mt][3] = *(const uint32_t*)(al_p + 8 * APITCH + 16);
            }
#pragma unroll
            for (int nb = 0; nb < 8; nb++) {
                const char* br = smem + BH_OFF + (nb * 8 + lr) * APITCH + kb * 32 + lk;
                uint32_t bh[2], bl[2];
                bh[0] = *(const uint32_t*)br;
                bh[1] = *(const uint32_t*)(br + 16);
                bl[0] = *(const uint32_t*)(br + (BL_OFF - BH_OFF));
                bl[1] = *(const uint32_t*)(br + (BL_OFF - BH_OFF) + 16);
#pragma unroll
                for (int mt = 0; mt < 2; mt++) {
                    mma16816(d[mt][nb], ah[mt], bh);
                    mma16816(d[mt][nb], al[mt], bh);
                    mma16816(d[mt][nb], ah[mt], bl);
                }
            }
        }
    }

    // epilogue: bias + relu, write NCHW fp32
    const int lr = l >> 2;
    const int lc = (l & 3) * 2;
#pragma unroll
    for (int mt = 0; mt < 2; mt++) {
#pragma unroll
        for (int nb = 0; nb < 8; nb++) {
#pragma unroll
            for (int j = 0; j < 4; j++) {
                int n = nb * 8 + lc + (j & 1);
                int m = w * 32 + mt * 16 + lr + ((j >> 1) * 8);
                float v = d[mt][nb][j] + *(const float*)(smem + BIAS_OFF + n * 4);
                g_x[((long)(b * 64 + n)) * 4096 + y0 * 64 + m] = fmaxf(v, 0.f);
            }
        }
    }
}

// ---------------------------------------------------------------------------
// Packed fp32x2 helpers (kept for conv2/fuse)
// ---------------------------------------------------------------------------
__device__ __forceinline__ unsigned long long f32x2_fma(
    unsigned long long a, unsigned long long b, unsigned long long c)
{
    unsigned long long d;
    asm("fma.rn.f32x2 %0, %1, %2, %3;" : "=l"(d) : "l"(a), "l"(b), "l"(c));
    return d;
}
__device__ __forceinline__ unsigned long long f32x2_pack(float lo, float hi)
{
    unsigned long long d;
    asm("mov.b64 %0, {%1, %2};" : "=l"(d) : "f"(lo), "f"(hi));
    return d;
}
__device__ __forceinline__ float2 f32x2_unpack(unsigned long long v)
{
    float2 r;
    asm("mov.b64 {%0, %1}, %2;" : "=f"(r.x), "=f"(r.y) : "l"(v));
    return r;
}

#define CIC 8

// ---------------------------------------------------------------------------
// conv2 (CUDA-core): 3x3 conv + sigmoid, CO=16
// ---------------------------------------------------------------------------
__global__ __launch_bounds__(256) void conv2_kernel(
    const float* __restrict__ in, const float* __restrict__ w,
    const float* __restrict__ bias, float* __restrict__ out)
{
    const int bi = blockIdx.x;
    const int ytile = bi & 7;
    const int b = bi >> 3;

    __shared__ float s_in[CIC * 10 * 66];
    __shared__ unsigned long long s_w2[CIC * 9 * 16];

    const int tid = threadIdx.x;
    const int row0 = tid >> 6;
    const int col = tid & 63;

    unsigned long long acc2[16];
#pragma unroll
    for (int j = 0; j < 16; j++) acc2[j] = 0ull;

    const float* in_b = in + (long)b * (Fc * HW);

    for (int cic = 0; cic < Fc; cic += CIC) {
        __syncthreads();
        for (int idx = tid; idx < CIC * 10 * 66; idx += 256) {
            int ci = idx / 660;
            int rem = idx - ci * 660;
            int r = rem / 66;
            int c = rem - r * 66;
            int gy = ytile * 8 + r - 1;
            int gx = c - 1;
            float v = 0.f;
            if (gy >= 0 && gy < Hh && gx >= 0 && gx < Ww)
                v = in_b[(cic + ci) * HW + gy * Ww + gx];
            s_in[idx] = v;
        }
        for (int idx = tid; idx < CIC * 9 * 16; idx += 256) {
            int co = idx & 15;
            int rest = idx >> 4;
            int tap = rest % 9;
            int ci = rest / 9;
            float wv = w[co * (Fc * 9) + (cic + ci) * 9 + tap];
            s_w2[idx] = f32x2_pack(wv, wv);
        }
        __syncthreads();

        for (int ci = 0; ci < CIC; ci++) {
            const float* sp = s_in + ci * 660;
#pragma unroll
            for (int tap = 0; tap < 9; tap++) {
                const int dy = tap / 3, dx = tap % 3;
                float ilo = sp[(row0 + dy) * 66 + col + dx];
                float ihi = sp[(row0 + 4 + dy) * 66 + col + dx];
                unsigned long long a = f32x2_pack(ilo, ihi);
                const ulonglong2* wp = (const ulonglong2*)(s_w2 + (ci * 9 + tap) * 16);
#pragma unroll
                for (int q = 0; q < 8; q++) {
                    ulonglong2 wv = wp[q];
                    acc2[q * 2 + 0] = f32x2_fma(a, wv.x, acc2[q * 2 + 0]);
                    acc2[q * 2 + 1] = f32x2_fma(a, wv.y, acc2[q * 2 + 1]);
                }
            }
        }
    }

#pragma unroll
    for (int j = 0; j < 16; j++) {
        float bj = bias[j];
        float2 v = f32x2_unpack(acc2[j]);
        v.x = 1.f / (1.f + __expf(-(v.x + bj)));
        v.y = 1.f / (1.f + __expf(-(v.y + bj)));
        float* ob = out + ((long)b * 16 + j) * HW;
        int y_lo = ytile * 8 + row0;
        ob[y_lo * Ww + col] = v.x;
        ob[(y_lo + 4) * Ww + col] = v.y;
    }
}

// ---------------------------------------------------------------------------
// Fused cs-GEMM + relu-reduction
// ---------------------------------------------------------------------------
#define FUSE_SMEM_FLOATS (64 * 64 + 16 * 128 + 128 * 68)
#define FUSE_SMEM_BYTES (FUSE_SMEM_FLOATS * 4)

__global__ __launch_bounds__(256) void fuse_kernel(
    const float* __restrict__ state, const float* __restrict__ attn,
    const float* __restrict__ c3_w, const float* __restrict__ c3_b)
{
    extern __shared__ float fsm[];
    float* w_t = fsm;
    float* attn_s = fsm + 4096;
    float* cs_s = fsm + 6144;

    const int b = blockIdx.x >> 5;
    const int chunk = blockIdx.x & 31;
    const int pbase = chunk * 128;
    const int tid = threadIdx.x;

#pragma unroll
    for (int k = 0; k < 16; k++) {
        int idx = tid + k * 256;
        float v = c3_w[idx];
        int o = idx >> 6, f = idx & 63;
        w_t[f * 64 + o] = v;
    }
#pragma unroll
    for (int k = 0; k < 8; k++) {
        int idx = tid + k * 256;
        int e = idx >> 7, pp = idx & 127;
        attn_s[idx] = attn[((long)b * 16 + e) * HW + pbase + pp];
    }
    __syncthreads();

    {
        const int pp = tid & 127;
        const int oh = tid >> 7;
        unsigned long long c2[16];
#pragma unroll
        for (int j = 0; j < 16; j++) c2[j] = 0ull;
        const float* sbp = state + (long)b * (Fc * HW) + pbase + pp;
#pragma unroll 4
        for (int f = 0; f < Fc; f++) {
            float s = sbp[f * HW];
            unsigned long long a = f32x2_pack(s, s);
            const ulonglong2* wp = (const ulonglong2*)(w_t + f * 64 + oh * 32);
#pragma unroll
            for (int q = 0; q < 8; q++) {
                ulonglong2 wv = wp[q];
                c2[q * 2 + 0] = f32x2_fma(a, wv.x, c2[q * 2 + 0]);
                c2[q * 2 + 1] = f32x2_fma(a, wv.y, c2[q * 2 + 1]);
            }
        }
        unsigned long long* cp = (unsigned long long*)(cs_s + pp * 68 + oh * 32);
#pragma unroll
        for (int j = 0; j < 16; j++) cp[j] = c2[j];
    }
    __syncthreads();

    {
        const int e = tid >> 4;
        const int oq = tid & 15;
        const float4 bias = ((const float4*)c3_b)[oq];
        float4 acc = make_float4(0.f, 0.f, 0.f, 0.f);
        const float* arow = attn_s + e * 128;
#pragma unroll 4
        for (int pp = 0; pp < 128; pp++) {
            float a = arow[pp];
            float4 cv = *(const float4*)(cs_s + pp * 68 + oq * 4);
            acc.x += fmaxf(fmaf(a, cv.x, bias.x), 0.f);
            acc.y += fmaxf(fmaf(a, cv.y, bias.y), 0.f);
            acc.z += fmaxf(fmaf(a, cv.z, bias.z), 0.f);
            acc.w += fmaxf(fmaf(a, cv.w, bias.w), 0.f);
        }
        float4* po = (float4*)(g_partials + ((long)(b * 32 + chunk)) * 1024 + e * 64 + oq * 4);
        *po = acc;
    }
}

__global__ __launch_bounds__(256) void reduce_kernel(
    const float* __restrict__ c3_b, float* __restrict__ out)
{
    int gid = blockIdx.x * 256 + threadIdx.x;
    int o = gid & 63;
    float sum = 260.f * fmaxf(c3_b[o], 0.f);
    int b = gid >> 10;
    int eo = gid & 1023;
    const float* p = g_partials + (long)b * 32 * 1024 + eo;
#pragma unroll
    for (int c = 0; c < 32; c++) sum += p[c * 1024];
    out[gid] = sum * (1.f / 4356.f);
}

// ---------------------------------------------------------------------------
extern "C" void kernel_launch(void* const* d_in, const int* in_sizes, int n_in,
                              void* d_out, int out_size)
{
    const float* state = (const float*)d_in[0];
    const float* pre_w = (const float*)d_in[1];
    const float* pre_b = (const float*)d_in[2];
    const float* attn_w = (const float*)d_in[3];
    const float* attn_b = (const float*)d_in[4];
    const float* c3_w = (const float*)d_in[5];
    const float* c3_b = (const float*)d_in[6];

    float* out = (float*)d_out;
    float* attn = out + Bn * Ec * Fc;

    void* p_x = nullptr;
    cudaGetSymbolAddress(&p_x, g_x);
    float* xbuf = (float*)p_x;

    cudaFuncSetAttribute(fuse_kernel, cudaFuncAttributeMaxDynamicSharedMemorySize,
                         FUSE_SMEM_BYTES);
    cudaFuncSetAttribute(conv1_mma_kernel, cudaFuncAttributeMaxDynamicSharedMemorySize,
                         CONV1_SMEM);

    // prep: weights + state to bf16 hi/lo layouts
    wprep_kernel<<<72, 256>>>(pre_w);
    xprep_kernel<<<Bn * 64, 256>>>(state);
    // conv1 on HMMA (mma.sync): 512 blocks of (2 rows x 64 cols) x 64 co
    conv1_mma_kernel<<<Bn * 32, 128, CONV1_SMEM>>>(pre_b);
    // conv2: x -> attn (sigmoid), CO=16 (CUDA-core)
    conv2_kernel<<<Bn * 8, 256>>>(xbuf, attn_w, attn_b, attn);
    // fused cs-GEMM + relu-reduction partials
    fuse_kernel<<<Bn * 32, 256, FUSE_SMEM_BYTES>>>(state, attn, c3_w, c3_b);
    // final reduce + pad term
    reduce_kernel<<<64, 256>>>(c3_b, out);
}

// round 5
// speedup vs baseline: 1.4139x; 1.0551x over previous
#include <cuda_runtime.h>
#include <cuda_bf16.h>
#include <cstdint>

// Problem constants
#define Bn 16
#define Fc 64
#define Ec 16
#define Hh 64
#define Ww 64
#define HW (Hh * Ww)

// Scratch (device globals: allocation-free rule)
__device__ float g_partials[Bn * 32 * 16 * 64];          // fuse partial sums
__device__ __align__(16) uint32_t g_xhi[Bn * HW * 32];   // state bf16-hi [b][pix][ci2]
__device__ __align__(16) uint32_t g_xlo[Bn * HW * 32];   // state bf16-lo
__device__ __align__(16) uint32_t g_x2hi[Bn * HW * 32];  // relu(conv1) bf16-hi [b][pix][ci2]
__device__ __align__(16) uint32_t g_x2lo[Bn * HW * 32];  // relu(conv1) bf16-lo
__device__ __align__(16) uint8_t  g_wtile[9 * 16384];    // conv1 W [tap][hi|lo][co64][ci]
__device__ __align__(16) uint8_t  g_wtile2[9 * 4096];    // conv2 W [tap][hi|lo][co16][ci]

// ---------------------------------------------------------------------------
// mma.sync m16n8k16 row.col f32.bf16.bf16.f32 (baseline PTX, OK at compute_103)
// ---------------------------------------------------------------------------
__device__ __forceinline__ void mma16816(float* d, const uint32_t* a, const uint32_t* b)
{
    asm volatile(
        "mma.sync.aligned.m16n8k16.row.col.f32.bf16.bf16.f32 "
        "{%0,%1,%2,%3}, {%4,%5,%6,%7}, {%8,%9}, {%0,%1,%2,%3};"
        : "+f"(d[0]), "+f"(d[1]), "+f"(d[2]), "+f"(d[3])
        : "r"(a[0]), "r"(a[1]), "r"(a[2]), "r"(a[3]), "r"(b[0]), "r"(b[1]));
}

__device__ __forceinline__ uint32_t pack_bf16x2(float v0, float v1)
{
    __nv_bfloat16 h0 = __float2bfloat16(v0);
    __nv_bfloat16 h1 = __float2bfloat16(v1);
    return ((uint32_t)__bfloat16_as_ushort(h1) << 16) | __bfloat16_as_ushort(h0);
}

// ---------------------------------------------------------------------------
// Prep: conv1 weights -> bf16 hi/lo tiles per tap, [tap][part][co][ci]
// ---------------------------------------------------------------------------
__global__ __launch_bounds__(256) void wprep_kernel(const float* __restrict__ w)
{
    int idx = blockIdx.x * 256 + threadIdx.x;  // (tap, co64, ci-pair)
    int tap = idx >> 11;
    int rem = idx & 2047;
    int co = rem >> 5, ci2 = rem & 31;
    float v0 = w[(co * 64 + 2 * ci2) * 9 + tap];
    float v1 = w[(co * 64 + 2 * ci2 + 1) * 9 + tap];
    __nv_bfloat16 h0 = __float2bfloat16(v0);
    __nv_bfloat16 h1 = __float2bfloat16(v1);
    float l0 = v0 - __bfloat162float(h0);
    float l1 = v1 - __bfloat162float(h1);
    *(uint32_t*)(g_wtile + tap * 16384 + co * 128 + ci2 * 4) =
        ((uint32_t)__bfloat16_as_ushort(h1) << 16) | __bfloat16_as_ushort(h0);
    *(uint32_t*)(g_wtile + tap * 16384 + 8192 + co * 128 + ci2 * 4) = pack_bf16x2(l0, l1);
}

// Prep: conv2 weights (E=16 x F=64 x 3 x 3) -> [tap][part][co16][ci]
__global__ __launch_bounds__(256) void wprep2_kernel(const float* __restrict__ w)
{
    int idx = blockIdx.x * 256 + threadIdx.x;  // 0..4607 = (tap, co16, ci-pair)
    if (idx >= 9 * 512) return;
    int tap = idx >> 9;
    int rem = idx & 511;
    int co = rem >> 5, ci2 = rem & 31;
    float v0 = w[(co * 64 + 2 * ci2) * 9 + tap];
    float v1 = w[(co * 64 + 2 * ci2 + 1) * 9 + tap];
    __nv_bfloat16 h0 = __float2bfloat16(v0);
    __nv_bfloat16 h1 = __float2bfloat16(v1);
    float l0 = v0 - __bfloat162float(h0);
    float l1 = v1 - __bfloat162float(h1);
    *(uint32_t*)(g_wtile2 + tap * 4096 + co * 128 + ci2 * 4) =
        ((uint32_t)__bfloat16_as_ushort(h1) << 16) | __bfloat16_as_ushort(h0);
    *(uint32_t*)(g_wtile2 + tap * 4096 + 2048 + co * 128 + ci2 * 4) = pack_bf16x2(l0, l1);
}

// ---------------------------------------------------------------------------
// Prep: state NCHW fp32 -> [b][pix][ci] bf16 hi/lo (pixel-major, 128B/pixel)
// ---------------------------------------------------------------------------
__global__ __launch_bounds__(256) void xprep_kernel(const float* __restrict__ state)
{
    __shared__ float s[64 * 65];
    int b = blockIdx.x >> 6, y = blockIdx.x & 63;
    int tid = threadIdx.x;
#pragma unroll
    for (int k = 0; k < 16; k++) {
        int idx = tid + k * 256;
        int ci = idx >> 6, x = idx & 63;
        s[ci * 65 + x] = state[((long)(b * 64 + ci) * 64 + y) * 64 + x];
    }
    __syncthreads();
#pragma unroll
    for (int k = 0; k < 8; k++) {
        int idx = tid + k * 256;
        int x = idx >> 5, j = idx & 31;
        float v0 = s[(2 * j) * 65 + x];
        float v1 = s[(2 * j + 1) * 65 + x];
        __nv_bfloat16 h0 = __float2bfloat16(v0);
        __nv_bfloat16 h1 = __float2bfloat16(v1);
        float l0 = v0 - __bfloat162float(h0);
        float l1 = v1 - __bfloat162float(h1);
        long o = ((long)b * 4096 + y * 64 + x) * 32 + j;
        g_xhi[o] = ((uint32_t)__bfloat16_as_ushort(h1) << 16) | __bfloat16_as_ushort(h0);
        g_xlo[o] = pack_bf16x2(l0, l1);
    }
}

// ---------------------------------------------------------------------------
// conv1 via mma.sync: block = (b, 2-row strip) -> D[128 pix][64 co].
// Epilogue: bias+relu, emit bf16 hi/lo pixel-major (feeds conv2 directly).
// ---------------------------------------------------------------------------
#define APITCH 144
#define AH_OFF 0
#define AL_OFF (128 * APITCH)
#define BH_OFF (2 * 128 * APITCH)
#define BL_OFF (BH_OFF + 64 * APITCH)
#define BIAS_OFF (BL_OFF + 64 * APITCH)
#define CONV1_SMEM (BIAS_OFF + 256)

__global__ __launch_bounds__(128) void conv1_mma_kernel(const float* __restrict__ bias)
{
    extern __shared__ char smem[];
    const int tid = threadIdx.x;
    const int w = tid >> 5;
    const int l = tid & 31;
    const int b = blockIdx.x >> 5;
    const int y0 = (blockIdx.x & 31) * 2;

    if (tid < 64) *(float*)(smem + BIAS_OFF + tid * 4) = bias[tid];

    float d[2][8][4];
#pragma unroll
    for (int mt = 0; mt < 2; mt++)
#pragma unroll
        for (int nb = 0; nb < 8; nb++)
#pragma unroll
            for (int j = 0; j < 4; j++) d[mt][nb][j] = 0.f;

    const uint4* xh4 = (const uint4*)g_xhi;
    const uint4* xl4 = (const uint4*)g_xlo;

    for (int tap = 0; tap < 9; tap++) {
        const int dy = tap / 3 - 1;
        const int dx = tap % 3 - 1;
        if (tap) __syncthreads();

        // stage A: thread = pixel m (0..127); 128B of ci hi/lo per pixel
        {
            const int y = y0 + (tid >> 6) + dy;
            const int xx = (tid & 63) + dx;
            const bool ok = ((unsigned)y < 64u) && ((unsigned)xx < 64u);
            const long pix8 = ((long)b * 4096 + y * 64 + xx) * 8;
            char* arh = smem + AH_OFF + tid * APITCH;
            char* arl = smem + AL_OFF + tid * APITCH;
#pragma unroll
            for (int q = 0; q < 8; q++) {
                uint4 vh = make_uint4(0, 0, 0, 0), vl = make_uint4(0, 0, 0, 0);
                if (ok) { vh = xh4[pix8 + q]; vl = xl4[pix8 + q]; }
                *(uint4*)(arh + q * 16) = vh;
                *(uint4*)(arl + q * 16) = vl;
            }
        }
        // stage B: [co][ci] rows, hi then lo
        {
            const uint4* wsrc = (const uint4*)(g_wtile + tap * 16384);
#pragma unroll
            for (int i = 0; i < 4; i++) {
                int idx = tid + i * 128;
                int row = idx >> 3, c = idx & 7;
                *(uint4*)(smem + BH_OFF + row * APITCH + c * 16) = wsrc[idx];
            }
#pragma unroll
            for (int i = 0; i < 4; i++) {
                int idx = tid + i * 128;
                int row = idx >> 3, c = idx & 7;
                *(uint4*)(smem + BL_OFF + row * APITCH + c * 16) = wsrc[512 + idx];
            }
        }
        __syncthreads();

        const int lr = l >> 2;
        const int lk = (l & 3) * 4;
#pragma unroll
        for (int kb = 0; kb < 4; kb++) {
            uint32_t ah[2][4], al[2][4];
#pragma unroll
            for (int mt = 0; mt < 2; mt++) {
                const char* ar = smem + AH_OFF + (w * 32 + mt * 16 + lr) * APITCH + kb * 32 + lk;
                ah[mt][0] = *(const uint32_t*)ar;
                ah[mt][1] = *(const uint32_t*)(ar + 8 * APITCH);
                ah[mt][2] = *(const uint32_t*)(ar + 16);
                ah[mt][3] = *(const uint32_t*)(ar + 8 * APITCH + 16);
                const char* alp = ar + (AL_OFF - AH_OFF);
                al[mt][0] = *(const uint32_t*)alp;
                al[mt][1] = *(const uint32_t*)(alp + 8 * APITCH);
                al[mt][2] = *(const uint32_t*)(alp + 16);
                al[mt][3] = *(const uint32_t*)(alp + 8 * APITCH + 16);
            }
#pragma unroll
            for (int nb = 0; nb < 8; nb++) {
                const char* br = smem + BH_OFF + (nb * 8 + lr) * APITCH + kb * 32 + lk;
                uint32_t bh[2], bl[2];
                bh[0] = *(const uint32_t*)br;
                bh[1] = *(const uint32_t*)(br + 16);
                bl[0] = *(const uint32_t*)(br + (BL_OFF - BH_OFF));
                bl[1] = *(const uint32_t*)(br + (BL_OFF - BH_OFF) + 16);
#pragma unroll
                for (int mt = 0; mt < 2; mt++) {
                    mma16816(d[mt][nb], ah[mt], bh);
                    mma16816(d[mt][nb], al[mt], bh);
                    mma16816(d[mt][nb], ah[mt], bl);
                }
            }
        }
    }

    // epilogue: bias+relu -> bf16 hi/lo pixel-major [b][pix][ci2]
    const int lr = l >> 2;
    const int lc2 = l & 3;   // ci-pair within nb
#pragma unroll
    for (int mt = 0; mt < 2; mt++) {
#pragma unroll
        for (int nb = 0; nb < 8; nb++) {
            float b0 = *(const float*)(smem + BIAS_OFF + (nb * 8 + lc2 * 2) * 4);
            float b1 = *(const float*)(smem + BIAS_OFF + (nb * 8 + lc2 * 2 + 1) * 4);
#pragma unroll
            for (int row = 0; row < 2; row++) {
                int m = w * 32 + mt * 16 + lr + row * 8;
                float v0 = fmaxf(d[mt][nb][row * 2 + 0] + b0, 0.f);
                float v1 = fmaxf(d[mt][nb][row * 2 + 1] + b1, 0.f);
                __nv_bfloat16 h0 = __float2bfloat16(v0);
                __nv_bfloat16 h1 = __float2bfloat16(v1);
                float l0 = v0 - __bfloat162float(h0);
                float l1 = v1 - __bfloat162float(h1);
                long o = ((long)b * 4096 + y0 * 64 + m) * 32 + nb * 4 + lc2;
                g_x2hi[o] = ((uint32_t)__bfloat16_as_ushort(h1) << 16) |
                            __bfloat16_as_ushort(h0);
                g_x2lo[o] = pack_bf16x2(l0, l1);
            }
        }
    }
}

// ---------------------------------------------------------------------------
// conv2 via mma.sync: block = (b, 2-row strip) -> D[128 pix][16 e], sigmoid.
// ---------------------------------------------------------------------------
#define B2H_OFF (2 * 128 * APITCH)              /* 36864 */
#define B2L_OFF (B2H_OFF + 16 * APITCH)         /* 39168 */
#define BIAS2_OFF (B2L_OFF + 16 * APITCH)       /* 41472 */
#define CONV2_SMEM (BIAS2_OFF + 64)

__global__ __launch_bounds__(128) void conv2_mma_kernel(
    const float* __restrict__ bias, float* __restrict__ attn)
{
    extern __shared__ char smem[];
    const int tid = threadIdx.x;
    const int w = tid >> 5;
    const int l = tid & 31;
    const int b = blockIdx.x >> 5;
    const int y0 = (blockIdx.x & 31) * 2;

    if (tid < 16) *(float*)(smem + BIAS2_OFF + tid * 4) = bias[tid];

    float d[2][2][4];
#pragma unroll
    for (int mt = 0; mt < 2; mt++)
#pragma unroll
        for (int nb = 0; nb < 2; nb++)
#pragma unroll
            for (int j = 0; j < 4; j++) d[mt][nb][j] = 0.f;

    const uint4* xh4 = (const uint4*)g_x2hi;
    const uint4* xl4 = (const uint4*)g_x2lo;

    for (int tap = 0; tap < 9; tap++) {
        const int dy = tap / 3 - 1;
        const int dx = tap % 3 - 1;
        if (tap) __syncthreads();

        {
            const int y = y0 + (tid >> 6) + dy;
            const int xx = (tid & 63) + dx;
            const bool ok = ((unsigned)y < 64u) && ((unsigned)xx < 64u);
            const long pix8 = ((long)b * 4096 + y * 64 + xx) * 8;
            char* arh = smem + AH_OFF + tid * APITCH;
            char* arl = smem + AL_OFF + tid * APITCH;
#pragma unroll
            for (int q = 0; q < 8; q++) {
                uint4 vh = make_uint4(0, 0, 0, 0), vl = make_uint4(0, 0, 0, 0);
                if (ok) { vh = xh4[pix8 + q]; vl = xl4[pix8 + q]; }
                *(uint4*)(arh + q * 16) = vh;
                *(uint4*)(arl + q * 16) = vl;
            }
        }
        // B tiles: 16 rows x 8 uint4, hi + lo
        {
            const uint4* wsrc = (const uint4*)(g_wtile2 + tap * 4096);
            int row = tid >> 3, c = tid & 7;
            *(uint4*)(smem + B2H_OFF + row * APITCH + c * 16) = wsrc[tid];
            *(uint4*)(smem + B2L_OFF + row * APITCH + c * 16) = wsrc[128 + tid];
        }
        __syncthreads();

        const int lr = l >> 2;
        const int lk = (l & 3) * 4;
#pragma unroll
        for (int kb = 0; kb < 4; kb++) {
            uint32_t ah[2][4], al[2][4];
#pragma unroll
            for (int mt = 0; mt < 2; mt++) {
                const char* ar = smem + AH_OFF + (w * 32 + mt * 16 + lr) * APITCH + kb * 32 + lk;
                ah[mt][0] = *(const uint32_t*)ar;
                ah[mt][1] = *(const uint32_t*)(ar + 8 * APITCH);
                ah[mt][2] = *(const uint32_t*)(ar + 16);
                ah[mt][3] = *(const uint32_t*)(ar + 8 * APITCH + 16);
                const char* alp = ar + (AL_OFF - AH_OFF);
                al[mt][0] = *(const uint32_t*)alp;
                al[mt][1] = *(const uint32_t*)(alp + 8 * APITCH);
                al[mt][2] = *(const uint32_t*)(alp + 16);
                al[mt][3] = *(const uint32_t*)(alp + 8 * APITCH + 16);
            }
#pragma unroll
            for (int nb = 0; nb < 2; nb++) {
                const char* br = smem + B2H_OFF + (nb * 8 + lr) * APITCH + kb * 32 + lk;
                uint32_t bh[2], bl[2];
                bh[0] = *(const uint32_t*)br;
                bh[1] = *(const uint32_t*)(br + 16);
                bl[0] = *(const uint32_t*)(br + (B2L_OFF - B2H_OFF));
                bl[1] = *(const uint32_t*)(br + (B2L_OFF - B2H_OFF) + 16);
#pragma unroll
                for (int mt = 0; mt < 2; mt++) {
                    mma16816(d[mt][nb], ah[mt], bh);
                    mma16816(d[mt][nb], al[mt], bh);
                    mma16816(d[mt][nb], ah[mt], bl);
                }
            }
        }
    }

    // epilogue: bias + sigmoid -> attn NCHW fp32
    const int lr = l >> 2;
    const int lc = (l & 3) * 2;
#pragma unroll
    for (int mt = 0; mt < 2; mt++) {
#pragma unroll
        for (int nb = 0; nb < 2; nb++) {
#pragma unroll
            for (int j = 0; j < 4; j++) {
                int n = nb * 8 + lc + (j & 1);
                int m = w * 32 + mt * 16 + lr + ((j >> 1) * 8);
                float v = d[mt][nb][j] + *(const float*)(smem + BIAS2_OFF + n * 4);
                v = 1.f / (1.f + __expf(-v));
                attn[((long)(b * 16 + n)) * 4096 + y0 * 64 + m] = v;
            }
        }
    }
}

// ---------------------------------------------------------------------------
// Packed fp32x2 helpers (for fuse)
// ---------------------------------------------------------------------------
__device__ __forceinline__ unsigned long long f32x2_fma(
    unsigned long long a, unsigned long long b, unsigned long long c)
{
    unsigned long long d;
    asm("fma.rn.f32x2 %0, %1, %2, %3;" : "=l"(d) : "l"(a), "l"(b), "l"(c));
    return d;
}
__device__ __forceinline__ unsigned long long f32x2_pack(float lo, float hi)
{
    unsigned long long d;
    asm("mov.b64 %0, {%1, %2};" : "=l"(d) : "f"(lo), "f"(hi));
    return d;
}

// ---------------------------------------------------------------------------
// Fused cs-GEMM + relu-reduction
// ---------------------------------------------------------------------------
#define FUSE_SMEM_FLOATS (64 * 64 + 16 * 128 + 128 * 68)
#define FUSE_SMEM_BYTES (FUSE_SMEM_FLOATS * 4)

__global__ __launch_bounds__(256) void fuse_kernel(
    const float* __restrict__ state, const float* __restrict__ attn,
    const float* __restrict__ c3_w, const float* __restrict__ c3_b)
{
    extern __shared__ float fsm[];
    float* w_t = fsm;
    float* attn_s = fsm + 4096;
    float* cs_s = fsm + 6144;

    const int b = blockIdx.x >> 5;
    const int chunk = blockIdx.x & 31;
    const int pbase = chunk * 128;
    const int tid = threadIdx.x;

#pragma unroll
    for (int k = 0; k < 16; k++) {
        int idx = tid + k * 256;
        float v = c3_w[idx];
        int o = idx >> 6, f = idx & 63;
        w_t[f * 64 + o] = v;
    }
#pragma unroll
    for (int k = 0; k < 8; k++) {
        int idx = tid + k * 256;
        int e = idx >> 7, pp = idx & 127;
        attn_s[idx] = attn[((long)b * 16 + e) * HW + pbase + pp];
    }
    __syncthreads();

    {
        const int pp = tid & 127;
        const int oh = tid >> 7;
        unsigned long long c2[16];
#pragma unroll
        for (int j = 0; j < 16; j++) c2[j] = 0ull;
        const float* sbp = state + (long)b * (Fc * HW) + pbase + pp;
#pragma unroll 4
        for (int f = 0; f < Fc; f++) {
            float s = sbp[f * HW];
            unsigned long long a = f32x2_pack(s, s);
            const ulonglong2* wp = (const ulonglong2*)(w_t + f * 64 + oh * 32);
#pragma unroll
            for (int q = 0; q < 8; q++) {
                ulonglong2 wv = wp[q];
                c2[q * 2 + 0] = f32x2_fma(a, wv.x, c2[q * 2 + 0]);
                c2[q * 2 + 1] = f32x2_fma(a, wv.y, c2[q * 2 + 1]);
            }
        }
        unsigned long long* cp = (unsigned long long*)(cs_s + pp * 68 + oh * 32);
#pragma unroll
        for (int j = 0; j < 16; j++) cp[j] = c2[j];
    }
    __syncthreads();

    {
        const int e = tid >> 4;
        const int oq = tid & 15;
        const float4 bias = ((const float4*)c3_b)[oq];
        float4 acc = make_float4(0.f, 0.f, 0.f, 0.f);
        const float* arow = attn_s + e * 128;
#pragma unroll 4
        for (int pp = 0; pp < 128; pp++) {
            float a = arow[pp];
            float4 cv = *(const float4*)(cs_s + pp * 68 + oq * 4);
            acc.x += fmaxf(fmaf(a, cv.x, bias.x), 0.f);
            acc.y += fmaxf(fmaf(a, cv.y, bias.y), 0.f);
            acc.z += fmaxf(fmaf(a, cv.z, bias.z), 0.f);
            acc.w += fmaxf(fmaf(a, cv.w, bias.w), 0.f);
        }
        float4* po = (float4*)(g_partials + ((long)(b * 32 + chunk)) * 1024 + e * 64 + oq * 4);
        *po = acc;
    }
}

__global__ __launch_bounds__(256) void reduce_kernel(
    const float* __restrict__ c3_b, float* __restrict__ out)
{
    int gid = blockIdx.x * 256 + threadIdx.x;
    int o = gid & 63;
    float sum = 260.f * fmaxf(c3_b[o], 0.f);
    int b = gid >> 10;
    int eo = gid & 1023;
    const float* p = g_partials + (long)b * 32 * 1024 + eo;
#pragma unroll
    for (int c = 0; c < 32; c++) sum += p[c * 1024];
    out[gid] = sum * (1.f / 4356.f);
}

// ---------------------------------------------------------------------------
extern "C" void kernel_launch(void* const* d_in, const int* in_sizes, int n_in,
                              void* d_out, int out_size)
{
    const float* state = (const float*)d_in[0];
    const float* pre_w = (const float*)d_in[1];
    const float* pre_b = (const float*)d_in[2];
    const float* attn_w = (const float*)d_in[3];
    const float* attn_b = (const float*)d_in[4];
    const float* c3_w = (const float*)d_in[5];
    const float* c3_b = (const float*)d_in[6];

    float* out = (float*)d_out;
    float* attn = out + Bn * Ec * Fc;

    cudaFuncSetAttribute(fuse_kernel, cudaFuncAttributeMaxDynamicSharedMemorySize,
                         FUSE_SMEM_BYTES);
    cudaFuncSetAttribute(conv1_mma_kernel, cudaFuncAttributeMaxDynamicSharedMemorySize,
                         CONV1_SMEM);
    cudaFuncSetAttribute(conv2_mma_kernel, cudaFuncAttributeMaxDynamicSharedMemorySize,
                         CONV2_SMEM);

    // prep: weights + state to bf16 hi/lo layouts
    wprep_kernel<<<72, 256>>>(pre_w);
    wprep2_kernel<<<18, 256>>>(attn_w);
    xprep_kernel<<<Bn * 64, 256>>>(state);
    // conv1 on HMMA: writes x as bf16 hi/lo pixel-major
    conv1_mma_kernel<<<Bn * 32, 128, CONV1_SMEM>>>(pre_b);
    // conv2 on HMMA: x -> attn (sigmoid), straight into d_out
    conv2_mma_kernel<<<Bn * 32, 128, CONV2_SMEM>>>(attn_b, attn);
    // fused cs-GEMM + relu-reduction partials
    fuse_kernel<<<Bn * 32, 256, FUSE_SMEM_BYTES>>>(state, attn, c3_w, c3_b);
    // final reduce + pad term
    reduce_kernel<<<64, 256>>>(c3_b, out);
}

// round 6
// speedup vs baseline: 2.0384x; 1.4417x over previous
#include <cuda_runtime.h>
#include <cuda_bf16.h>
#include <cstdint>

// Problem constants
#define Bn 16
#define Fc 64
#define Ec 16
#define Hh 64
#define Ww 64
#define HW (Hh * Ww)

// Scratch (device globals: allocation-free rule)
__device__ float g_partials[Bn * 32 * 16 * 64];          // fuse partial sums
__device__ __align__(16) uint32_t g_xhi[Bn * HW * 32];   // state bf16-hi [b][pix][ci2]
__device__ __align__(16) uint32_t g_xlo[Bn * HW * 32];   // state bf16-lo
__device__ __align__(16) uint32_t g_x2hi[Bn * HW * 32];  // relu(conv1) bf16-hi
__device__ __align__(16) uint32_t g_x2lo[Bn * HW * 32];  // relu(conv1) bf16-lo
__device__ __align__(16) uint8_t  g_wtile[9 * 16384];    // conv1 W swizzled [tap][part][co][ci]
__device__ __align__(16) uint8_t  g_wtile2[9 * 4096];    // conv2 W swizzled [tap][part][co][ci]

// ---------------------------------------------------------------------------
// mma.sync + ldmatrix (baseline PTX, legal at compute_103)
// ---------------------------------------------------------------------------
__device__ __forceinline__ void mma16816(float* d, const uint32_t* a, const uint32_t* b)
{
    asm volatile(
        "mma.sync.aligned.m16n8k16.row.col.f32.bf16.bf16.f32 "
        "{%0,%1,%2,%3}, {%4,%5,%6,%7}, {%8,%9}, {%0,%1,%2,%3};"
        : "+f"(d[0]), "+f"(d[1]), "+f"(d[2]), "+f"(d[3])
        : "r"(a[0]), "r"(a[1]), "r"(a[2]), "r"(a[3]), "r"(b[0]), "r"(b[1]));
}

__device__ __forceinline__ void ldsm4(uint32_t* r, uint32_t addr)
{
    asm volatile("ldmatrix.sync.aligned.m8n8.x4.shared.b16 {%0,%1,%2,%3}, [%4];"
                 : "=r"(r[0]), "=r"(r[1]), "=r"(r[2]), "=r"(r[3]) : "r"(addr));
}

__device__ __forceinline__ uint32_t smem_u32(const void* p)
{
    uint32_t a;
    asm("{ .reg .u64 t; cvta.to.shared.u64 t, %1; cvt.u32.u64 %0, t; }" : "=r"(a) : "l"(p));
    return a;
}

__device__ __forceinline__ uint32_t pack_bf16x2(float v0, float v1)
{
    __nv_bfloat16 h0 = __float2bfloat16(v0);
    __nv_bfloat16 h1 = __float2bfloat16(v1);
    return ((uint32_t)__bfloat16_as_ushort(h1) << 16) | __bfloat16_as_ushort(h0);
}

// ---------------------------------------------------------------------------
// Prep: conv1 weights -> swizzled bf16 hi/lo [tap][part][co][ci]
// swizzle: 16B chunk q stored at (q ^ (co & 7))
// ---------------------------------------------------------------------------
__global__ __launch_bounds__(256) void wprep_kernel(const float* __restrict__ w)
{
    int idx = blockIdx.x * 256 + threadIdx.x;  // (tap, co64, ci-pair)
    int tap = idx >> 11;
    int rem = idx & 2047;
    int co = rem >> 5, ci2 = rem & 31;
    float v0 = w[(co * 64 + 2 * ci2) * 9 + tap];
    float v1 = w[(co * 64 + 2 * ci2 + 1) * 9 + tap];
    __nv_bfloat16 h0 = __float2bfloat16(v0);
    __nv_bfloat16 h1 = __float2bfloat16(v1);
    float l0 = v0 - __bfloat162float(h0);
    float l1 = v1 - __bfloat162float(h1);
    int q = ci2 >> 2, wd = ci2 & 3;
    int sw = ((q ^ (co & 7)) << 4) + wd * 4;
    *(uint32_t*)(g_wtile + tap * 16384 + co * 128 + sw) =
        ((uint32_t)__bfloat16_as_ushort(h1) << 16) | __bfloat16_as_ushort(h0);
    *(uint32_t*)(g_wtile + tap * 16384 + 8192 + co * 128 + sw) = pack_bf16x2(l0, l1);
}

__global__ __launch_bounds__(256) void wprep2_kernel(const float* __restrict__ w)
{
    int idx = blockIdx.x * 256 + threadIdx.x;  // (tap, co16, ci-pair)
    if (idx >= 9 * 512) return;
    int tap = idx >> 9;
    int rem = idx & 511;
    int co = rem >> 5, ci2 = rem & 31;
    float v0 = w[(co * 64 + 2 * ci2) * 9 + tap];
    float v1 = w[(co * 64 + 2 * ci2 + 1) * 9 + tap];
    __nv_bfloat16 h0 = __float2bfloat16(v0);
    __nv_bfloat16 h1 = __float2bfloat16(v1);
    float l0 = v0 - __bfloat162float(h0);
    float l1 = v1 - __bfloat162float(h1);
    int q = ci2 >> 2, wd = ci2 & 3;
    int sw = ((q ^ (co & 7)) << 4) + wd * 4;
    *(uint32_t*)(g_wtile2 + tap * 4096 + co * 128 + sw) =
        ((uint32_t)__bfloat16_as_ushort(h1) << 16) | __bfloat16_as_ushort(h0);
    *(uint32_t*)(g_wtile2 + tap * 4096 + 2048 + co * 128 + sw) = pack_bf16x2(l0, l1);
}

// ---------------------------------------------------------------------------
// Prep: state NCHW fp32 -> [b][pix][ci] bf16 hi/lo (pixel-major, 128B/pixel)
// ---------------------------------------------------------------------------
__global__ __launch_bounds__(256) void xprep_kernel(const float* __restrict__ state)
{
    __shared__ float s[64 * 65];
    int b = blockIdx.x >> 6, y = blockIdx.x & 63;
    int tid = threadIdx.x;
#pragma unroll
    for (int k = 0; k < 16; k++) {
        int idx = tid + k * 256;
        int ci = idx >> 6, x = idx & 63;
        s[ci * 65 + x] = state[((long)(b * 64 + ci) * 64 + y) * 64 + x];
    }
    __syncthreads();
#pragma unroll
    for (int k = 0; k < 8; k++) {
        int idx = tid + k * 256;
        int x = idx >> 5, j = idx & 31;
        float v0 = s[(2 * j) * 65 + x];
        float v1 = s[(2 * j + 1) * 65 + x];
        __nv_bfloat16 h0 = __float2bfloat16(v0);
        __nv_bfloat16 h1 = __float2bfloat16(v1);
        float l0 = v0 - __bfloat162float(h0);
        float l1 = v1 - __bfloat162float(h1);
        long o = ((long)b * 4096 + y * 64 + x) * 32 + j;
        g_xhi[o] = ((uint32_t)__bfloat16_as_ushort(h1) << 16) | __bfloat16_as_ushort(h0);
        g_xlo[o] = pack_bf16x2(l0, l1);
    }
}

// ---------------------------------------------------------------------------
// Shared conv template pieces: A-halo (4 rows x 66 cols) staged once,
// swizzled 128B pixel rows, ldmatrix fragment loads, zero mainloop syncs.
// ---------------------------------------------------------------------------
#define AHALO_PIX 264            /* 4 * 66 */
#define AH_OFF 0
#define AL_OFF 33792             /* 264*128 */
#define B1_OFF 67584
#define BIAS1_OFF (B1_OFF + 147456)            /* 215040 */
#define CONV1_SMEM (BIAS1_OFF + 256)           /* 215296 */
#define B2_OFF 67584
#define BIAS2_OFF (B2_OFF + 36864)             /* 104448 */
#define CONV2_SMEM (BIAS2_OFF + 64)            /* 104512 */

// Stage A halo: rows y0-1..y0+2, cols -1..64, hi+lo, swizzled
__device__ __forceinline__ void stage_halo(
    char* smem, const uint4* xh4, const uint4* xl4, int b, int y0, int tid)
{
    for (int p = tid; p < AHALO_PIX; p += 128) {
        int r = p / 66, c = p - r * 66;
        int y = y0 - 1 + r;
        int x = c - 1;
        bool ok = ((unsigned)y < 64u) && ((unsigned)x < 64u);
        long pix8 = ((long)b * 4096 + y * 64 + x) * 8;
        char* dh = smem + AH_OFF + p * 128;
        char* dl = smem + AL_OFF + p * 128;
        int key = p & 7;
#pragma unroll
        for (int q = 0; q < 8; q++) {
            uint4 vh = make_uint4(0, 0, 0, 0), vl = make_uint4(0, 0, 0, 0);
            if (ok) { vh = xh4[pix8 + q]; vl = xl4[pix8 + q]; }
            int sw = (q ^ key) << 4;
            *(uint4*)(dh + sw) = vh;
            *(uint4*)(dl + sw) = vl;
        }
    }
}

// ---------------------------------------------------------------------------
// conv1: block = (b, 2-row strip) -> D[128 pix][64 co]; relu; bf16 hi/lo out
// ---------------------------------------------------------------------------
__global__ __launch_bounds__(128) void conv1_mma_kernel(const float* __restrict__ bias)
{
    extern __shared__ char smem[];
    const uint32_t sb = smem_u32(smem);
    const int tid = threadIdx.x;
    const int w = tid >> 5;
    const int l = tid & 31;
    const int b = blockIdx.x >> 5;
    const int y0 = (blockIdx.x & 31) * 2;

    if (tid < 64) *(float*)(smem + BIAS1_OFF + tid * 4) = bias[tid];

    // stage all 9 B tiles (pre-swizzled in gmem; linear copy)
    {
        const uint4* wsrc = (const uint4*)g_wtile;
        uint4* dst = (uint4*)(smem + B1_OFF);
#pragma unroll
        for (int i = 0; i < 72; i++) dst[tid + i * 128] = wsrc[tid + i * 128];
    }
    stage_halo(smem, (const uint4*)g_xhi, (const uint4*)g_xlo, b, y0, tid);
    __syncthreads();

    float d[2][8][4];
#pragma unroll
    for (int mt = 0; mt < 2; mt++)
#pragma unroll
        for (int nb = 0; nb < 8; nb++)
#pragma unroll
            for (int j = 0; j < 4; j++) d[mt][nb][j] = 0.f;

    // per-lane invariants
    const int lane7 = l & 7;
    const int hi16 = (l >> 4) & 1;            // A chunk selector
    int ax[2], aly[2];
#pragma unroll
    for (int mt = 0; mt < 2; mt++) {
        int mrow = w * 32 + mt * 16 + (l & 8) + lane7;
        ax[mt] = mrow & 63;
        aly[mt] = mrow >> 6;
    }
    const int brow = ((l >> 4) & 1) * 8 + lane7;   // + nbp*16
    const int bcb = (l >> 3) & 1;                  // B chunk bit

#pragma unroll
    for (int tap = 0; tap < 9; tap++) {
        const int dy = tap / 3 - 1;
        const int dx = tap % 3 - 1;
        uint32_t abase[2];
        int akey[2];
#pragma unroll
        for (int mt = 0; mt < 2; mt++) {
            int p = (aly[mt] + dy + 1) * 66 + ax[mt] + dx + 1;
            akey[mt] = p & 7;
            abase[mt] = sb + p * 128;
        }
        const uint32_t btap = sb + B1_OFF + tap * 16384;
#pragma unroll
        for (int kb = 0; kb < 4; kb++) {
            uint32_t ah[2][4], al[2][4];
#pragma unroll
            for (int mt = 0; mt < 2; mt++) {
                int chunk = kb * 2 + hi16;
                uint32_t sw = (uint32_t)((chunk ^ akey[mt]) << 4);
                ldsm4(ah[mt], abase[mt] + sw);
                ldsm4(al[mt], abase[mt] + AL_OFF + sw);
            }
#pragma unroll
            for (int nbp = 0; nbp < 4; nbp++) {
                int n = nbp * 16 + brow;
                uint32_t baddr = btap + n * 128 +
                                 (uint32_t)((((kb * 2 + bcb) ^ (n & 7))) << 4);
                uint32_t bh[4], bl[4];
                ldsm4(bh, baddr);
                ldsm4(bl, baddr + 8192);
#pragma unroll
                for (int mt = 0; mt < 2; mt++) {
                    mma16816(d[mt][2 * nbp], ah[mt], bh);
                    mma16816(d[mt][2 * nbp], al[mt], bh);
                    mma16816(d[mt][2 * nbp], ah[mt], bl);
                    mma16816(d[mt][2 * nbp + 1], ah[mt], bh + 2);
                    mma16816(d[mt][2 * nbp + 1], al[mt], bh + 2);
                    mma16816(d[mt][2 * nbp + 1], ah[mt], bl + 2);
                }
            }
        }
    }

    // epilogue: bias+relu -> bf16 hi/lo pixel-major [b][pix][ci2]
    const int lr = l >> 2;
    const int lc2 = l & 3;
#pragma unroll
    for (int mt = 0; mt < 2; mt++) {
#pragma unroll
        for (int nb = 0; nb < 8; nb++) {
            float b0 = *(const float*)(smem + BIAS1_OFF + (nb * 8 + lc2 * 2) * 4);
            float b1 = *(const float*)(smem + BIAS1_OFF + (nb * 8 + lc2 * 2 + 1) * 4);
#pragma unroll
            for (int row = 0; row < 2; row++) {
                int m = w * 32 + mt * 16 + lr + row * 8;
                float v0 = fmaxf(d[mt][nb][row * 2 + 0] + b0, 0.f);
                float v1 = fmaxf(d[mt][nb][row * 2 + 1] + b1, 0.f);
                __nv_bfloat16 h0 = __float2bfloat16(v0);
                __nv_bfloat16 h1 = __float2bfloat16(v1);
                float l0 = v0 - __bfloat162float(h0);
                float l1 = v1 - __bfloat162float(h1);
                long o = ((long)b * 4096 + y0 * 64 + m) * 32 + nb * 4 + lc2;
                g_x2hi[o] = ((uint32_t)__bfloat16_as_ushort(h1) << 16) |
                            __bfloat16_as_ushort(h0);
                g_x2lo[o] = pack_bf16x2(l0, l1);
            }
        }
    }
}

// ---------------------------------------------------------------------------
// conv2: block = (b, 2-row strip) -> D[128 pix][16 e]; sigmoid into d_out
// ---------------------------------------------------------------------------
__global__ __launch_bounds__(128) void conv2_mma_kernel(
    const float* __restrict__ bias, float* __restrict__ attn)
{
    extern __shared__ char smem[];
    const uint32_t sb = smem_u32(smem);
    const int tid = threadIdx.x;
    const int w = tid >> 5;
    const int l = tid & 31;
    const int b = blockIdx.x >> 5;
    const int y0 = (blockIdx.x & 31) * 2;

    if (tid < 16) *(float*)(smem + BIAS2_OFF + tid * 4) = bias[tid];

    {
        const uint4* wsrc = (const uint4*)g_wtile2;
        uint4* dst = (uint4*)(smem + B2_OFF);
#pragma unroll
        for (int i = 0; i < 18; i++) dst[tid + i * 128] = wsrc[tid + i * 128];
    }
    stage_halo(smem, (const uint4*)g_x2hi, (const uint4*)g_x2lo, b, y0, tid);
    __syncthreads();

    float d[2][2][4];
#pragma unroll
    for (int mt = 0; mt < 2; mt++)
#pragma unroll
        for (int nb = 0; nb < 2; nb++)
#pragma unroll
            for (int j = 0; j < 4; j++) d[mt][nb][j] = 0.f;

    const int lane7 = l & 7;
    const int hi16 = (l >> 4) & 1;
    int ax[2], aly[2];
#pragma unroll
    for (int mt = 0; mt < 2; mt++) {
        int mrow = w * 32 + mt * 16 + (l & 8) + lane7;
        ax[mt] = mrow & 63;
        aly[mt] = mrow >> 6;
    }
    const int brow = ((l >> 4) & 1) * 8 + lane7;
    const int bcb = (l >> 3) & 1;

#pragma unroll
    for (int tap = 0; tap < 9; tap++) {
        const int dy = tap / 3 - 1;
        const int dx = tap % 3 - 1;
        uint32_t abase[2];
        int akey[2];
#pragma unroll
        for (int mt = 0; mt < 2; mt++) {
            int p = (aly[mt] + dy + 1) * 66 + ax[mt] + dx + 1;
            akey[mt] = p & 7;
            abase[mt] = sb + p * 128;
        }
        const uint32_t btap = sb + B2_OFF + tap * 4096;
#pragma unroll
        for (int kb = 0; kb < 4; kb++) {
            uint32_t ah[2][4], al[2][4];
#pragma unroll
            for (int mt = 0; mt < 2; mt++) {
                int chunk = kb * 2 + hi16;
                uint32_t sw = (uint32_t)((chunk ^ akey[mt]) << 4);
                ldsm4(ah[mt], abase[mt] + sw);
                ldsm4(al[mt], abase[mt] + AL_OFF + sw);
            }
            {
                int n = brow;   // nbp = 0 only (N=16)
                uint32_t baddr = btap + n * 128 +
                                 (uint32_t)((((kb * 2 + bcb) ^ (n & 7))) << 4);
                uint32_t bh[4], bl[4];
                ldsm4(bh, baddr);
                ldsm4(bl, baddr + 2048);
#pragma unroll
                for (int mt = 0; mt < 2; mt++) {
                    mma16816(d[mt][0], ah[mt], bh);
                    mma16816(d[mt][0], al[mt], bh);
                    mma16816(d[mt][0], ah[mt], bl);
                    mma16816(d[mt][1], ah[mt], bh + 2);
                    mma16816(d[mt][1], al[mt], bh + 2);
                    mma16816(d[mt][1], ah[mt], bl + 2);
                }
            }
        }
    }

    // epilogue: bias + sigmoid -> attn NCHW fp32 (straight into d_out)
    const int lr = l >> 2;
    const int lc = (l & 3) * 2;
#pragma unroll
    for (int mt = 0; mt < 2; mt++) {
#pragma unroll
        for (int nb = 0; nb < 2; nb++) {
#pragma unroll
            for (int j = 0; j < 4; j++) {
                int n = nb * 8 + lc + (j & 1);
                int m = w * 32 + mt * 16 + lr + ((j >> 1) * 8);
                float v = d[mt][nb][j] + *(const float*)(smem + BIAS2_OFF + n * 4);
                v = 1.f / (1.f + __expf(-v));
                attn[((long)(b * 16 + n)) * 4096 + y0 * 64 + m] = v;
            }
        }
    }
}

// ---------------------------------------------------------------------------
// Packed fp32x2 helpers (for fuse)
// ---------------------------------------------------------------------------
__device__ __forceinline__ unsigned long long f32x2_fma(
    unsigned long long a, unsigned long long b, unsigned long long c)
{
    unsigned long long d;
    asm("fma.rn.f32x2 %0, %1, %2, %3;" : "=l"(d) : "l"(a), "l"(b), "l"(c));
    return d;
}
__device__ __forceinline__ unsigned long long f32x2_pack(float lo, float hi)
{
    unsigned long long d;
    asm("mov.b64 %0, {%1, %2};" : "=l"(d) : "f"(lo), "f"(hi));
    return d;
}

// ---------------------------------------------------------------------------
// Fused cs-GEMM + relu-reduction
// ---------------------------------------------------------------------------
#define FUSE_SMEM_FLOATS (64 * 64 + 16 * 128 + 128 * 68)
#define FUSE_SMEM_BYTES (FUSE_SMEM_FLOATS * 4)

__global__ __launch_bounds__(256) void fuse_kernel(
    const float* __restrict__ state, const float* __restrict__ attn,
    const float* __restrict__ c3_w, const float* __restrict__ c3_b)
{
    extern __shared__ float fsm[];
    float* w_t = fsm;
    float* attn_s = fsm + 4096;
    float* cs_s = fsm + 6144;

    const int b = blockIdx.x >> 5;
    const int chunk = blockIdx.x & 31;
    const int pbase = chunk * 128;
    const int tid = threadIdx.x;

#pragma unroll
    for (int k = 0; k < 16; k++) {
        int idx = tid + k * 256;
        float v = c3_w[idx];
        int o = idx >> 6, f = idx & 63;
        w_t[f * 64 + o] = v;
    }
#pragma unroll
    for (int k = 0; k < 8; k++) {
        int idx = tid + k * 256;
        int e = idx >> 7, pp = idx & 127;
        attn_s[idx] = attn[((long)b * 16 + e) * HW + pbase + pp];
    }
    __syncthreads();

    {
        const int pp = tid & 127;
        const int oh = tid >> 7;
        unsigned long long c2[16];
#pragma unroll
        for (int j = 0; j < 16; j++) c2[j] = 0ull;
        const float* sbp = state + (long)b * (Fc * HW) + pbase + pp;
#pragma unroll 4
        for (int f = 0; f < Fc; f++) {
            float s = sbp[f * HW];
            unsigned long long a = f32x2_pack(s, s);
            const ulonglong2* wp = (const ulonglong2*)(w_t + f * 64 + oh * 32);
#pragma unroll
            for (int q = 0; q < 8; q++) {
                ulonglong2 wv = wp[q];
                c2[q * 2 + 0] = f32x2_fma(a, wv.x, c2[q * 2 + 0]);
                c2[q * 2 + 1] = f32x2_fma(a, wv.y, c2[q * 2 + 1]);
            }
        }
        unsigned long long* cp = (unsigned long long*)(cs_s + pp * 68 + oh * 32);
#pragma unroll
        for (int j = 0; j < 16; j++) cp[j] = c2[j];
    }
    __syncthreads();

    {
        const int e = tid >> 4;
        const int oq = tid & 15;
        const float4 bias = ((const float4*)c3_b)[oq];
        float4 acc = make_float4(0.f, 0.f, 0.f, 0.f);
        const float* arow = attn_s + e * 128;
#pragma unroll 4
        for (int pp = 0; pp < 128; pp++) {
            float a = arow[pp];
            float4 cv = *(const float4*)(cs_s + pp * 68 + oq * 4);
            acc.x += fmaxf(fmaf(a, cv.x, bias.x), 0.f);
            acc.y += fmaxf(fmaf(a, cv.y, bias.y), 0.f);
            acc.z += fmaxf(fmaf(a, cv.z, bias.z), 0.f);
            acc.w += fmaxf(fmaf(a, cv.w, bias.w), 0.f);
        }
        float4* po = (float4*)(g_partials + ((long)(b * 32 + chunk)) * 1024 + e * 64 + oq * 4);
        *po = acc;
    }
}

__global__ __launch_bounds__(256) void reduce_kernel(
    const float* __restrict__ c3_b, float* __restrict__ out)
{
    int gid = blockIdx.x * 256 + threadIdx.x;
    int o = gid & 63;
    float sum = 260.f * fmaxf(c3_b[o], 0.f);
    int b = gid >> 10;
    int eo = gid & 1023;
    const float* p = g_partials + (long)b * 32 * 1024 + eo;
#pragma unroll
    for (int c = 0; c < 32; c++) sum += p[c * 1024];
    out[gid] = sum * (1.f / 4356.f);
}

// ---------------------------------------------------------------------------
extern "C" void kernel_launch(void* const* d_in, const int* in_sizes, int n_in,
                              void* d_out, int out_size)
{
    const float* state = (const float*)d_in[0];
    const float* pre_w = (const float*)d_in[1];
    const float* pre_b = (const float*)d_in[2];
    const float* attn_w = (const float*)d_in[3];
    const float* attn_b = (const float*)d_in[4];
    const float* c3_w = (const float*)d_in[5];
    const float* c3_b = (const float*)d_in[6];

    float* out = (float*)d_out;
    float* attn = out + Bn * Ec * Fc;

    cudaFuncSetAttribute(fuse_kernel, cudaFuncAttributeMaxDynamicSharedMemorySize,
                         FUSE_SMEM_BYTES);
    cudaFuncSetAttribute(conv1_mma_kernel, cudaFuncAttributeMaxDynamicSharedMemorySize,
                         CONV1_SMEM);
    cudaFuncSetAttribute(conv2_mma_kernel, cudaFuncAttributeMaxDynamicSharedMemorySize,
                         CONV2_SMEM);

    // prep: weights + state to swizzled bf16 hi/lo layouts
    wprep_kernel<<<72, 256>>>(pre_w);
    wprep2_kernel<<<18, 256>>>(attn_w);
    xprep_kernel<<<Bn * 64, 256>>>(state);
    // conv1 on HMMA: halo staged once, all-tap B resident, ldmatrix loads
    conv1_mma_kernel<<<Bn * 32, 128, CONV1_SMEM>>>(pre_b);
    // conv2 on HMMA: x -> attn (sigmoid) straight into d_out
    conv2_mma_kernel<<<Bn * 32, 128, CONV2_SMEM>>>(attn_b, attn);
    // fused cs-GEMM + relu-reduction partials
    fuse_kernel<<<Bn * 32, 256, FUSE_SMEM_BYTES>>>(state, attn, c3_w, c3_b);
    // final reduce + pad term
    reduce_kernel<<<64, 256>>>(c3_b, out);
}

// round 7
// speedup vs baseline: 2.0441x; 1.0028x over previous
#include <cuda_runtime.h>
#include <cuda_bf16.h>
#include <cstdint>

// Problem constants
#define Bn 16
#define Fc 64
#define Ec 16
#define Hh 64
#define Ww 64
#define HW (Hh * Ww)

// Scratch (device globals: allocation-free rule)
__device__ float g_partials[Bn * 32 * 16 * 64];          // fuse partial sums
__device__ __align__(16) uint32_t g_xhi[Bn * HW * 32];   // state bf16-hi [b][pix][ci2]
__device__ __align__(16) uint32_t g_xlo[Bn * HW * 32];   // state bf16-lo
__device__ __align__(16) uint32_t g_x2hi[Bn * HW * 32];  // relu(conv1) bf16-hi
__device__ __align__(16) uint32_t g_x2lo[Bn * HW * 32];  // relu(conv1) bf16-lo
__device__ __align__(16) uint8_t  g_wtile[9 * 16384];    // conv1 W swizzled [tap][part][co][ci]
__device__ __align__(16) uint8_t  g_wtile2[9 * 4096];    // conv2 W swizzled [tap][part][co][ci]

// ---------------------------------------------------------------------------
// mma.sync + ldmatrix (baseline PTX, legal at compute_103)
// ---------------------------------------------------------------------------
__device__ __forceinline__ void mma16816(float* d, const uint32_t* a, const uint32_t* b)
{
    asm volatile(
        "mma.sync.aligned.m16n8k16.row.col.f32.bf16.bf16.f32 "
        "{%0,%1,%2,%3}, {%4,%5,%6,%7}, {%8,%9}, {%0,%1,%2,%3};"
        : "+f"(d[0]), "+f"(d[1]), "+f"(d[2]), "+f"(d[3])
        : "r"(a[0]), "r"(a[1]), "r"(a[2]), "r"(a[3]), "r"(b[0]), "r"(b[1]));
}

__device__ __forceinline__ void ldsm4(uint32_t* r, uint32_t addr)
{
    asm volatile("ldmatrix.sync.aligned.m8n8.x4.shared.b16 {%0,%1,%2,%3}, [%4];"
                 : "=r"(r[0]), "=r"(r[1]), "=r"(r[2]), "=r"(r[3]) : "r"(addr));
}

__device__ __forceinline__ uint32_t smem_u32(const void* p)
{
    uint32_t a;
    asm("{ .reg .u64 t; cvta.to.shared.u64 t, %1; cvt.u32.u64 %0, t; }" : "=r"(a) : "l"(p));
    return a;
}

__device__ __forceinline__ uint32_t pack_bf16x2(float v0, float v1)
{
    __nv_bfloat16 h0 = __float2bfloat16(v0);
    __nv_bfloat16 h1 = __float2bfloat16(v1);
    return ((uint32_t)__bfloat16_as_ushort(h1) << 16) | __bfloat16_as_ushort(h0);
}

// ---------------------------------------------------------------------------
// Prep: conv1 weights -> swizzled bf16 hi/lo [tap][part][co][ci]
// swizzle: 16B chunk q stored at (q ^ (co & 7))
// ---------------------------------------------------------------------------
__global__ __launch_bounds__(256) void wprep_kernel(const float* __restrict__ w)
{
    int idx = blockIdx.x * 256 + threadIdx.x;  // (tap, co64, ci-pair)
    int tap = idx >> 11;
    int rem = idx & 2047;
    int co = rem >> 5, ci2 = rem & 31;
    float v0 = w[(co * 64 + 2 * ci2) * 9 + tap];
    float v1 = w[(co * 64 + 2 * ci2 + 1) * 9 + tap];
    __nv_bfloat16 h0 = __float2bfloat16(v0);
    __nv_bfloat16 h1 = __float2bfloat16(v1);
    float l0 = v0 - __bfloat162float(h0);
    float l1 = v1 - __bfloat162float(h1);
    int q = ci2 >> 2, wd = ci2 & 3;
    int sw = ((q ^ (co & 7)) << 4) + wd * 4;
    *(uint32_t*)(g_wtile + tap * 16384 + co * 128 + sw) =
        ((uint32_t)__bfloat16_as_ushort(h1) << 16) | __bfloat16_as_ushort(h0);
    *(uint32_t*)(g_wtile + tap * 16384 + 8192 + co * 128 + sw) = pack_bf16x2(l0, l1);
}

__global__ __launch_bounds__(256) void wprep2_kernel(const float* __restrict__ w)
{
    int idx = blockIdx.x * 256 + threadIdx.x;  // (tap, co16, ci-pair)
    if (idx >= 9 * 512) return;
    int tap = idx >> 9;
    int rem = idx & 511;
    int co = rem >> 5, ci2 = rem & 31;
    float v0 = w[(co * 64 + 2 * ci2) * 9 + tap];
    float v1 = w[(co * 64 + 2 * ci2 + 1) * 9 + tap];
    __nv_bfloat16 h0 = __float2bfloat16(v0);
    __nv_bfloat16 h1 = __float2bfloat16(v1);
    float l0 = v0 - __bfloat162float(h0);
    float l1 = v1 - __bfloat162float(h1);
    int q = ci2 >> 2, wd = ci2 & 3;
    int sw = ((q ^ (co & 7)) << 4) + wd * 4;
    *(uint32_t*)(g_wtile2 + tap * 4096 + co * 128 + sw) =
        ((uint32_t)__bfloat16_as_ushort(h1) << 16) | __bfloat16_as_ushort(h0);
    *(uint32_t*)(g_wtile2 + tap * 4096 + 2048 + co * 128 + sw) = pack_bf16x2(l0, l1);
}

// ---------------------------------------------------------------------------
// Prep: state NCHW fp32 -> [b][pix][ci] bf16 hi/lo (pixel-major, 128B/pixel)
// ---------------------------------------------------------------------------
__global__ __launch_bounds__(256) void xprep_kernel(const float* __restrict__ state)
{
    __shared__ float s[64 * 65];
    int b = blockIdx.x >> 6, y = blockIdx.x & 63;
    int tid = threadIdx.x;
#pragma unroll
    for (int k = 0; k < 16; k++) {
        int idx = tid + k * 256;
        int ci = idx >> 6, x = idx & 63;
        s[ci * 65 + x] = state[((long)(b * 64 + ci) * 64 + y) * 64 + x];
    }
    __syncthreads();
#pragma unroll
    for (int k = 0; k < 8; k++) {
        int idx = tid + k * 256;
        int x = idx >> 5, j = idx & 31;
        float v0 = s[(2 * j) * 65 + x];
        float v1 = s[(2 * j + 1) * 65 + x];
        __nv_bfloat16 h0 = __float2bfloat16(v0);
        __nv_bfloat16 h1 = __float2bfloat16(v1);
        float l0 = v0 - __bfloat162float(h0);
        float l1 = v1 - __bfloat162float(h1);
        long o = ((long)b * 4096 + y * 64 + x) * 32 + j;
        g_xhi[o] = ((uint32_t)__bfloat16_as_ushort(h1) << 16) | __bfloat16_as_ushort(h0);
        g_xlo[o] = pack_bf16x2(l0, l1);
    }
}

// ---------------------------------------------------------------------------
// Shared conv pieces: A-halo (4 rows x 66 cols) staged once, swizzled 128B
// pixel rows, ldmatrix fragment loads, zero mainloop syncs.
// ---------------------------------------------------------------------------
#define AHALO_PIX 264            /* 4 * 66 */
#define AH_OFF 0
#define AL_OFF 33792             /* 264*128 */
#define B1_OFF 67584
#define BIAS1_OFF (B1_OFF + 147456)            /* 215040 */
#define CONV1_SMEM (BIAS1_OFF + 256)           /* 215296 */
#define B2_OFF 67584
#define BIAS2_OFF (B2_OFF + 36864)             /* 104448 */
#define CONV2_SMEM (BIAS2_OFF + 64)            /* 104512 */

// Stage A halo: rows y0-1..y0+2, cols -1..64, hi+lo, swizzled
template <int NT>
__device__ __forceinline__ void stage_halo(
    char* smem, const uint4* xh4, const uint4* xl4, int b, int y0, int tid)
{
    for (int p = tid; p < AHALO_PIX; p += NT) {
        int r = p / 66, c = p - r * 66;
        int y = y0 - 1 + r;
        int x = c - 1;
        bool ok = ((unsigned)y < 64u) && ((unsigned)x < 64u);
        long pix8 = ((long)b * 4096 + y * 64 + x) * 8;
        char* dh = smem + AH_OFF + p * 128;
        char* dl = smem + AL_OFF + p * 128;
        int key = p & 7;
#pragma unroll
        for (int q = 0; q < 8; q++) {
            uint4 vh = make_uint4(0, 0, 0, 0), vl = make_uint4(0, 0, 0, 0);
            if (ok) { vh = xh4[pix8 + q]; vl = xl4[pix8 + q]; }
            int sw = (q ^ key) << 4;
            *(uint4*)(dh + sw) = vh;
            *(uint4*)(dl + sw) = vl;
        }
    }
}

// ---------------------------------------------------------------------------
// conv1: 256 threads, 8 warps = (wm 0..3) x (wn 0..1); warp tile M=32 x N=32.
// block = (b, 2-row strip) -> D[128 pix][64 co]; relu; bf16 hi/lo out.
// ---------------------------------------------------------------------------
__global__ __launch_bounds__(256) void conv1_mma_kernel(const float* __restrict__ bias)
{
    extern __shared__ char smem[];
    const uint32_t sb = smem_u32(smem);
    const int tid = threadIdx.x;
    const int w8 = tid >> 5;
    const int wm = w8 & 3;
    const int wn = w8 >> 2;
    const int l = tid & 31;
    const int b = blockIdx.x >> 5;
    const int y0 = (blockIdx.x & 31) * 2;

    if (tid < 64) *(float*)(smem + BIAS1_OFF + tid * 4) = bias[tid];

    // stage all 9 B tiles (pre-swizzled in gmem; linear copy)
    {
        const uint4* wsrc = (const uint4*)g_wtile;
        uint4* dst = (uint4*)(smem + B1_OFF);
#pragma unroll
        for (int i = 0; i < 36; i++) dst[tid + i * 256] = wsrc[tid + i * 256];
    }
    stage_halo<256>(smem, (const uint4*)g_xhi, (const uint4*)g_xlo, b, y0, tid);
    __syncthreads();

    float d[2][4][4];
#pragma unroll
    for (int mt = 0; mt < 2; mt++)
#pragma unroll
        for (int nb = 0; nb < 4; nb++)
#pragma unroll
            for (int j = 0; j < 4; j++) d[mt][nb][j] = 0.f;

    // per-lane invariants
    const int lane7 = l & 7;
    const int hi16 = (l >> 4) & 1;            // A chunk selector
    int ax[2], aly[2];
#pragma unroll
    for (int mt = 0; mt < 2; mt++) {
        int mrow = wm * 32 + mt * 16 + (l & 8) + lane7;
        ax[mt] = mrow & 63;
        aly[mt] = mrow >> 6;
    }
    const int brow = ((l >> 4) & 1) * 8 + lane7;   // + nbp*16
    const int bcb = (l >> 3) & 1;                  // B chunk bit

#pragma unroll
    for (int tap = 0; tap < 9; tap++) {
        const int dy = tap / 3 - 1;
        const int dx = tap % 3 - 1;
        uint32_t abase[2];
        int akey[2];
#pragma unroll
        for (int mt = 0; mt < 2; mt++) {
            int p = (aly[mt] + dy + 1) * 66 + ax[mt] + dx + 1;
            akey[mt] = p & 7;
            abase[mt] = sb + p * 128;
        }
        const uint32_t btap = sb + B1_OFF + tap * 16384;
#pragma unroll
        for (int kb = 0; kb < 4; kb++) {
            uint32_t ah[2][4], al[2][4];
#pragma unroll
            for (int mt = 0; mt < 2; mt++) {
                int chunk = kb * 2 + hi16;
                uint32_t sw = (uint32_t)((chunk ^ akey[mt]) << 4);
                ldsm4(ah[mt], abase[mt] + sw);
                ldsm4(al[mt], abase[mt] + AL_OFF + sw);
            }
#pragma unroll
            for (int nbl = 0; nbl < 2; nbl++) {
                int nbp = wn * 2 + nbl;
                int n = nbp * 16 + brow;
                uint32_t baddr = btap + n * 128 +
                                 (uint32_t)((((kb * 2 + bcb) ^ (n & 7))) << 4);
                uint32_t bh[4], bl[4];
                ldsm4(bh, baddr);
                ldsm4(bl, baddr + 8192);
#pragma unroll
                for (int mt = 0; mt < 2; mt++) {
                    mma16816(d[mt][2 * nbl], ah[mt], bh);
                    mma16816(d[mt][2 * nbl], al[mt], bh);
                    mma16816(d[mt][2 * nbl], ah[mt], bl);
                    mma16816(d[mt][2 * nbl + 1], ah[mt], bh + 2);
                    mma16816(d[mt][2 * nbl + 1], al[mt], bh + 2);
                    mma16816(d[mt][2 * nbl + 1], ah[mt], bl + 2);
                }
            }
        }
    }

    // epilogue: bias+relu -> bf16 hi/lo pixel-major [b][pix][ci2]
    const int lr = l >> 2;
    const int lc2 = l & 3;
#pragma unroll
    for (int mt = 0; mt < 2; mt++) {
#pragma unroll
        for (int nbl = 0; nbl < 4; nbl++) {
            int nb = wn * 4 + nbl;
            float b0 = *(const float*)(smem + BIAS1_OFF + (nb * 8 + lc2 * 2) * 4);
            float b1 = *(const float*)(smem + BIAS1_OFF + (nb * 8 + lc2 * 2 + 1) * 4);
#pragma unroll
            for (int row = 0; row < 2; row++) {
                int m = wm * 32 + mt * 16 + lr + row * 8;
                float v0 = fmaxf(d[mt][nbl][row * 2 + 0] + b0, 0.f);
                float v1 = fmaxf(d[mt][nbl][row * 2 + 1] + b1, 0.f);
                __nv_bfloat16 h0 = __float2bfloat16(v0);
                __nv_bfloat16 h1 = __float2bfloat16(v1);
                float l0 = v0 - __bfloat162float(h0);
                float l1 = v1 - __bfloat162float(h1);
                long o = ((long)b * 4096 + y0 * 64 + m) * 32 + nb * 4 + lc2;
                g_x2hi[o] = ((uint32_t)__bfloat16_as_ushort(h1) << 16) |
                            __bfloat16_as_ushort(h0);
                g_x2lo[o] = pack_bf16x2(l0, l1);
            }
        }
    }
}

// ---------------------------------------------------------------------------
// conv2: block = (b, 2-row strip) -> D[128 pix][16 e]; sigmoid into d_out
// ---------------------------------------------------------------------------
__global__ __launch_bounds__(128) void conv2_mma_kernel(
    const float* __restrict__ bias, float* __restrict__ attn)
{
    extern __shared__ char smem[];
    const uint32_t sb = smem_u32(smem);
    const int tid = threadIdx.x;
    const int w = tid >> 5;
    const int l = tid & 31;
    const int b = blockIdx.x >> 5;
    const int y0 = (blockIdx.x & 31) * 2;

    if (tid < 16) *(float*)(smem + BIAS2_OFF + tid * 4) = bias[tid];

    {
        const uint4* wsrc = (const uint4*)g_wtile2;
        uint4* dst = (uint4*)(smem + B2_OFF);
#pragma unroll
        for (int i = 0; i < 18; i++) dst[tid + i * 128] = wsrc[tid + i * 128];
    }
    stage_halo<128>(smem, (const uint4*)g_x2hi, (const uint4*)g_x2lo, b, y0, tid);
    __syncthreads();

    float d[2][2][4];
#pragma unroll
    for (int mt = 0; mt < 2; mt++)
#pragma unroll
        for (int nb = 0; nb < 2; nb++)
#pragma unroll
            for (int j = 0; j < 4; j++) d[mt][nb][j] = 0.f;

    const int lane7 = l & 7;
    const int hi16 = (l >> 4) & 1;
    int ax[2], aly[2];
#pragma unroll
    for (int mt = 0; mt < 2; mt++) {
        int mrow = w * 32 + mt * 16 + (l & 8) + lane7;
        ax[mt] = mrow & 63;
        aly[mt] = mrow >> 6;
    }
    const int brow = ((l >> 4) & 1) * 8 + lane7;
    const int bcb = (l >> 3) & 1;

#pragma unroll
    for (int tap = 0; tap < 9; tap++) {
        const int dy = tap / 3 - 1;
        const int dx = tap % 3 - 1;
        uint32_t abase[2];
        int akey[2];
#pragma unroll
        for (int mt = 0; mt < 2; mt++) {
            int p = (aly[mt] + dy + 1) * 66 + ax[mt] + dx + 1;
            akey[mt] = p & 7;
            abase[mt] = sb + p * 128;
        }
        const uint32_t btap = sb + B2_OFF + tap * 4096;
#pragma unroll
        for (int kb = 0; kb < 4; kb++) {
            uint32_t ah[2][4], al[2][4];
#pragma unroll
            for (int mt = 0; mt < 2; mt++) {
                int chunk = kb * 2 + hi16;
                uint32_t sw = (uint32_t)((chunk ^ akey[mt]) << 4);
                ldsm4(ah[mt], abase[mt] + sw);
                ldsm4(al[mt], abase[mt] + AL_OFF + sw);
            }
            {
                int n = brow;   // single nbp (N=16)
                uint32_t baddr = btap + n * 128 +
                                 (uint32_t)((((kb * 2 + bcb) ^ (n & 7))) << 4);
                uint32_t bh[4], bl[4];
                ldsm4(bh, baddr);
                ldsm4(bl, baddr + 2048);
#pragma unroll
                for (int mt = 0; mt < 2; mt++) {
                    mma16816(d[mt][0], ah[mt], bh);
                    mma16816(d[mt][0], al[mt], bh);
                    mma16816(d[mt][0], ah[mt], bl);
                    mma16816(d[mt][1], ah[mt], bh + 2);
                    mma16816(d[mt][1], al[mt], bh + 2);
                    mma16816(d[mt][1], ah[mt], bl + 2);
                }
            }
        }
    }

    // epilogue: bias + sigmoid -> attn NCHW fp32 (straight into d_out)
    const int lr = l >> 2;
    const int lc = (l & 3) * 2;
#pragma unroll
    for (int mt = 0; mt < 2; mt++) {
#pragma unroll
        for (int nb = 0; nb < 2; nb++) {
#pragma unroll
            for (int j = 0; j < 4; j++) {
                int n = nb * 8 + lc + (j & 1);
                int m = w * 32 + mt * 16 + lr + ((j >> 1) * 8);
                float v = d[mt][nb][j] + *(const float*)(smem + BIAS2_OFF + n * 4);
                v = 1.f / (1.f + __expf(-v));
                attn[((long)(b * 16 + n)) * 4096 + y0 * 64 + m] = v;
            }
        }
    }
}

// ---------------------------------------------------------------------------
// Packed fp32x2 helpers (for fuse)
// ---------------------------------------------------------------------------
__device__ __forceinline__ unsigned long long f32x2_fma(
    unsigned long long a, unsigned long long b, unsigned long long c)
{
    unsigned long long d;
    asm("fma.rn.f32x2 %0, %1, %2, %3;" : "=l"(d) : "l"(a), "l"(b), "l"(c));
    return d;
}
__device__ __forceinline__ unsigned long long f32x2_pack(float lo, float hi)
{
    unsigned long long d;
    asm("mov.b64 %0, {%1, %2};" : "=l"(d) : "f"(lo), "f"(hi));
    return d;
}

// ---------------------------------------------------------------------------
// Fused cs-GEMM + relu-reduction
// ---------------------------------------------------------------------------
#define FUSE_SMEM_FLOATS (64 * 64 + 16 * 128 + 128 * 68)
#define FUSE_SMEM_BYTES (FUSE_SMEM_FLOATS * 4)

__global__ __launch_bounds__(256) void fuse_kernel(
    const float* __restrict__ state, const float* __restrict__ attn,
    const float* __restrict__ c3_w, const float* __restrict__ c3_b)
{
    extern __shared__ float fsm[];
    float* w_t = fsm;
    float* attn_s = fsm + 4096;
    float* cs_s = fsm + 6144;

    const int b = blockIdx.x >> 5;
    const int chunk = blockIdx.x & 31;
    const int pbase = chunk * 128;
    const int tid = threadIdx.x;

#pragma unroll
    for (int k = 0; k < 16; k++) {
        int idx = tid + k * 256;
        float v = c3_w[idx];
        int o = idx >> 6, f = idx & 63;
        w_t[f * 64 + o] = v;
    }
#pragma unroll
    for (int k = 0; k < 8; k++) {
        int idx = tid + k * 256;
        int e = idx >> 7, pp = idx & 127;
        attn_s[idx] = attn[((long)b * 16 + e) * HW + pbase + pp];
    }
    __syncthreads();

    {
        const int pp = tid & 127;
        const int oh = tid >> 7;
        unsigned long long c2[16];
#pragma unroll
        for (int j = 0; j < 16; j++) c2[j] = 0ull;
        const float* sbp = state + (long)b * (Fc * HW) + pbase + pp;
#pragma unroll 4
        for (int f = 0; f < Fc; f++) {
            float s = sbp[f * HW];
            unsigned long long a = f32x2_pack(s, s);
            const ulonglong2* wp = (const ulonglong2*)(w_t + f * 64 + oh * 32);
#pragma unroll
            for (int q = 0; q < 8; q++) {
                ulonglong2 wv = wp[q];
                c2[q * 2 + 0] = f32x2_fma(a, wv.x, c2[q * 2 + 0]);
                c2[q * 2 + 1] = f32x2_fma(a, wv.y, c2[q * 2 + 1]);
            }
        }
        unsigned long long* cp = (unsigned long long*)(cs_s + pp * 68 + oh * 32);
#pragma unroll
        for (int j = 0; j < 16; j++) cp[j] = c2[j];
    }
    __syncthreads();

    {
        const int e = tid >> 4;
        const int oq = tid & 15;
        const float4 bias = ((const float4*)c3_b)[oq];
        float4 acc = make_float4(0.f, 0.f, 0.f, 0.f);
        const float* arow = attn_s + e * 128;
#pragma unroll 4
        for (int pp = 0; pp < 128; pp++) {
            float a = arow[pp];
            float4 cv = *(const float4*)(cs_s + pp * 68 + oq * 4);
            acc.x += fmaxf(fmaf(a, cv.x, bias.x), 0.f);
            acc.y += fmaxf(fmaf(a, cv.y, bias.y), 0.f);
            acc.z += fmaxf(fmaf(a, cv.z, bias.z), 0.f);
            acc.w += fmaxf(fmaf(a, cv.w, bias.w), 0.f);
        }
        float4* po = (float4*)(g_partials + ((long)(b * 32 + chunk)) * 1024 + e * 64 + oq * 4);
        *po = acc;
    }
}

__global__ __launch_bounds__(256) void reduce_kernel(
    const float* __restrict__ c3_b, float* __restrict__ out)
{
    int gid = blockIdx.x * 256 + threadIdx.x;
    int o = gid & 63;
    float sum = 260.f * fmaxf(c3_b[o], 0.f);
    int b = gid >> 10;
    int eo = gid & 1023;
    const float* p = g_partials + (long)b * 32 * 1024 + eo;
#pragma unroll
    for (int c = 0; c < 32; c++) sum += p[c * 1024];
    out[gid] = sum * (1.f / 4356.f);
}

// ---------------------------------------------------------------------------
extern "C" void kernel_launch(void* const* d_in, const int* in_sizes, int n_in,
                              void* d_out, int out_size)
{
    const float* state = (const float*)d_in[0];
    const float* pre_w = (const float*)d_in[1];
    const float* pre_b = (const float*)d_in[2];
    const float* attn_w = (const float*)d_in[3];
    const float* attn_b = (const float*)d_in[4];
    const float* c3_w = (const float*)d_in[5];
    const float* c3_b = (const float*)d_in[6];

    float* out = (float*)d_out;
    float* attn = out + Bn * Ec * Fc;

    cudaFuncSetAttribute(fuse_kernel, cudaFuncAttributeMaxDynamicSharedMemorySize,
                         FUSE_SMEM_BYTES);
    cudaFuncSetAttribute(conv1_mma_kernel, cudaFuncAttributeMaxDynamicSharedMemorySize,
                         CONV1_SMEM);
    cudaFuncSetAttribute(conv2_mma_kernel, cudaFuncAttributeMaxDynamicSharedMemorySize,
                         CONV2_SMEM);

    // prep: weights + state to swizzled bf16 hi/lo layouts
    wprep_kernel<<<72, 256>>>(pre_w);
    wprep2_kernel<<<18, 256>>>(attn_w);
    xprep_kernel<<<Bn * 64, 256>>>(state);
    // conv1 on HMMA: 8 warps/CTA (2 per SMSP), halo+B staged once
    conv1_mma_kernel<<<Bn * 32, 256, CONV1_SMEM>>>(pre_b);
    // conv2 on HMMA: x -> attn (sigmoid) straight into d_out
    conv2_mma_kernel<<<Bn * 32, 128, CONV2_SMEM>>>(attn_b, attn);
    // fused cs-GEMM + relu-reduction partials
    fuse_kernel<<<Bn * 32, 256, FUSE_SMEM_BYTES>>>(state, attn, c3_w, c3_b);
    // final reduce + pad term
    reduce_kernel<<<64, 256>>>(c3_b, out);
}

// round 9
// speedup vs baseline: 2.6743x; 1.3083x over previous
#include <cuda_runtime.h>
#include <cuda_bf16.h>
#include <cstdint>

// Problem constants
#define Bn 16
#define Fc 64
#define Ec 16
#define Hh 64
#define Ww 64
#define HW (Hh * Ww)

// Scratch (device globals: allocation-free rule)
__device__ float g_partials[Bn * 32 * 16 * 64];          // fuse partial sums
__device__ __align__(16) uint32_t g_xhi[Bn * HW * 32];   // state bf16-hi [b][pix][ci2]
__device__ __align__(16) uint32_t g_xlo[Bn * HW * 32];   // state bf16-lo
__device__ __align__(16) uint32_t g_x2hi[Bn * HW * 32];  // relu(conv1) bf16-hi
__device__ __align__(16) uint32_t g_x2lo[Bn * HW * 32];  // relu(conv1) bf16-lo
__device__ __align__(16) uint8_t  g_wtile[9 * 16384];    // conv1 W swizzled [tap][part][co][ci]
__device__ __align__(16) uint8_t  g_wtile2[9 * 4096];    // conv2 W swizzled
__device__ __align__(16) uint8_t  g_wtile3[16384];       // c3_w swizzled [part][o][f]

// ---------------------------------------------------------------------------
// mma.sync + ldmatrix + cp.async (baseline PTX, legal at compute_103)
// ---------------------------------------------------------------------------
__device__ __forceinline__ void mma16816(float* d, const uint32_t* a, const uint32_t* b)
{
    asm volatile(
        "mma.sync.aligned.m16n8k16.row.col.f32.bf16.bf16.f32 "
        "{%0,%1,%2,%3}, {%4,%5,%6,%7}, {%8,%9}, {%0,%1,%2,%3};"
        : "+f"(d[0]), "+f"(d[1]), "+f"(d[2]), "+f"(d[3])
        : "r"(a[0]), "r"(a[1]), "r"(a[2]), "r"(a[3]), "r"(b[0]), "r"(b[1]));
}

__device__ __forceinline__ void ldsm4(uint32_t* r, uint32_t addr)
{
    asm volatile("ldmatrix.sync.aligned.m8n8.x4.shared.b16 {%0,%1,%2,%3}, [%4];"
                 : "=r"(r[0]), "=r"(r[1]), "=r"(r[2]), "=r"(r[3]) : "r"(addr));
}

__device__ __forceinline__ void cp16(uint32_t dst, const void* src)
{
    asm volatile("cp.async.cg.shared.global [%0], [%1], 16;" :: "r"(dst), "l"(src));
}
__device__ __forceinline__ void cp_commit()
{
    asm volatile("cp.async.commit_group;" ::: "memory");
}
template <int N>
__device__ __forceinline__ void cp_wait()
{
    asm volatile("cp.async.wait_group %0;" :: "n"(N) : "memory");
}

__device__ __forceinline__ uint32_t smem_u32(const void* p)
{
    uint32_t a;
    asm("{ .reg .u64 t; cvta.to.shared.u64 t, %1; cvt.u32.u64 %0, t; }" : "=r"(a) : "l"(p));
    return a;
}

__device__ __forceinline__ uint32_t pack_bf16x2(float v0, float v1)
{
    __nv_bfloat16 h0 = __float2bfloat16(v0);
    __nv_bfloat16 h1 = __float2bfloat16(v1);
    return ((uint32_t)__bfloat16_as_ushort(h1) << 16) | __bfloat16_as_ushort(h0);
}

// ---------------------------------------------------------------------------
// Weight prep (all three weight sets in one kernel; swizzle q ^= row&7)
// blocks 0..71: conv1 W; 72..89: conv2 W; 90..97: c3_w
// ---------------------------------------------------------------------------
__global__ __launch_bounds__(256) void wprep_all_kernel(
    const float* __restrict__ w1, const float* __restrict__ w2,
    const float* __restrict__ w3)
{
    int bi = blockIdx.x;
    if (bi < 72) {
        int idx = bi * 256 + threadIdx.x;          // (tap, co64, ci-pair)
        int tap = idx >> 11;
        int rem = idx & 2047;
        int co = rem >> 5, ci2 = rem & 31;
        float v0 = w1[(co * 64 + 2 * ci2) * 9 + tap];
        float v1 = w1[(co * 64 + 2 * ci2 + 1) * 9 + tap];
        __nv_bfloat16 h0 = __float2bfloat16(v0);
        __nv_bfloat16 h1 = __float2bfloat16(v1);
        int q = ci2 >> 2, wd = ci2 & 3;
        int sw = ((q ^ (co & 7)) << 4) + wd * 4;
        *(uint32_t*)(g_wtile + tap * 16384 + co * 128 + sw) =
            ((uint32_t)__bfloat16_as_ushort(h1) << 16) | __bfloat16_as_ushort(h0);
        *(uint32_t*)(g_wtile + tap * 16384 + 8192 + co * 128 + sw) =
            pack_bf16x2(v0 - __bfloat162float(h0), v1 - __bfloat162float(h1));
    } else if (bi < 90) {
        int idx = (bi - 72) * 256 + threadIdx.x;   // (tap, co16, ci-pair)
        if (idx >= 9 * 512) return;
        int tap = idx >> 9;
        int rem = idx & 511;
        int co = rem >> 5, ci2 = rem & 31;
        float v0 = w2[(co * 64 + 2 * ci2) * 9 + tap];
        float v1 = w2[(co * 64 + 2 * ci2 + 1) * 9 + tap];
        __nv_bfloat16 h0 = __float2bfloat16(v0);
        __nv_bfloat16 h1 = __float2bfloat16(v1);
        int q = ci2 >> 2, wd = ci2 & 3;
        int sw = ((q ^ (co & 7)) << 4) + wd * 4;
        *(uint32_t*)(g_wtile2 + tap * 4096 + co * 128 + sw) =
            ((uint32_t)__bfloat16_as_ushort(h1) << 16) | __bfloat16_as_ushort(h0);
        *(uint32_t*)(g_wtile2 + tap * 4096 + 2048 + co * 128 + sw) =
            pack_bf16x2(v0 - __bfloat162float(h0), v1 - __bfloat162float(h1));
    } else {
        int idx = (bi - 90) * 256 + threadIdx.x;   // (o64, f-pair)
        if (idx >= 2048) return;
        int o = idx >> 5, f2 = idx & 31;
        float v0 = w3[o * 64 + 2 * f2];
        float v1 = w3[o * 64 + 2 * f2 + 1];
        __nv_bfloat16 h0 = __float2bfloat16(v0);
        __nv_bfloat16 h1 = __float2bfloat16(v1);
        int q = f2 >> 2, wd = f2 & 3;
        int sw = ((q ^ (o & 7)) << 4) + wd * 4;
        *(uint32_t*)(g_wtile3 + o * 128 + sw) =
            ((uint32_t)__bfloat16_as_ushort(h1) << 16) | __bfloat16_as_ushort(h0);
        *(uint32_t*)(g_wtile3 + 8192 + o * 128 + sw) =
            pack_bf16x2(v0 - __bfloat162float(h0), v1 - __bfloat162float(h1));
    }
}

// ---------------------------------------------------------------------------
// Prep: state NCHW fp32 -> [b][pix][ci] bf16 hi/lo (pixel-major, 128B/pixel)
// ---------------------------------------------------------------------------
__global__ __launch_bounds__(256) void xprep_kernel(const float* __restrict__ state)
{
    __shared__ float s[64 * 65];
    int b = blockIdx.x >> 6, y = blockIdx.x & 63;
    int tid = threadIdx.x;
#pragma unroll
    for (int k = 0; k < 16; k++) {
        int idx = tid + k * 256;
        int ci = idx >> 6, x = idx & 63;
        s[ci * 65 + x] = state[((long)(b * 64 + ci) * 64 + y) * 64 + x];
    }
    __syncthreads();
#pragma unroll
    for (int k = 0; k < 8; k++) {
        int idx = tid + k * 256;
        int x = idx >> 5, j = idx & 31;
        float v0 = s[(2 * j) * 65 + x];
        float v1 = s[(2 * j + 1) * 65 + x];
        __nv_bfloat16 h0 = __float2bfloat16(v0);
        __nv_bfloat16 h1 = __float2bfloat16(v1);
        long o = ((long)b * 4096 + y * 64 + x) * 32 + j;
        g_xhi[o] = ((uint32_t)__bfloat16_as_ushort(h1) << 16) | __bfloat16_as_ushort(h0);
        g_xlo[o] = pack_bf16x2(v0 - __bfloat162float(h0), v1 - __bfloat162float(h1));
    }
}

// ---------------------------------------------------------------------------
// Conv smem layouts
// ---------------------------------------------------------------------------
#define AHALO_PIX 264            /* 4 * 66 */
#define AH_OFF 0
#define AL_OFF 33792             /* 264*128 */
#define B1_OFF 67584             /* 2 x 16KB double buffer */
#define BIAS1_OFF (B1_OFF + 32768)             /* 100352 */
#define CONV1_SMEM (BIAS1_OFF + 256)           /* 100608 */
#define B2_OFF 67584
#define BIAS2_OFF (B2_OFF + 36864)             /* 104448 */
#define CONV2_SMEM (BIAS2_OFF + 64)            /* 104512 */

template <int NT>
__device__ __forceinline__ void stage_halo(
    char* smem, const uint4* xh4, const uint4* xl4, int b, int y0, int tid)
{
    for (int p = tid; p < AHALO_PIX; p += NT) {
        int r = p / 66, c = p - r * 66;
        int y = y0 - 1 + r;
        int x = c - 1;
        bool ok = ((unsigned)y < 64u) && ((unsigned)x < 64u);
        long pix8 = ((long)b * 4096 + y * 64 + x) * 8;
        char* dh = smem + AH_OFF + p * 128;
        char* dl = smem + AL_OFF + p * 128;
        int key = p & 7;
#pragma unroll
        for (int q = 0; q < 8; q++) {
            uint4 vh = make_uint4(0, 0, 0, 0), vl = make_uint4(0, 0, 0, 0);
            if (ok) { vh = xh4[pix8 + q]; vl = xl4[pix8 + q]; }
            int sw = (q ^ key) << 4;
            *(uint4*)(dh + sw) = vh;
            *(uint4*)(dl + sw) = vl;
        }
    }
}

// ---------------------------------------------------------------------------
// conv1: 256 threads, 8 warps (wm 0..3 x wn 0..1), warp tile 32x32.
// B double-buffered via cp.async (tap stream); 2 CTAs/SM.
// ---------------------------------------------------------------------------
__global__ __launch_bounds__(256) void conv1_mma_kernel(const float* __restrict__ bias)
{
    extern __shared__ char smem[];
    const uint32_t sb = smem_u32(smem);
    const int tid = threadIdx.x;
    const int w8 = tid >> 5;
    const int wm = w8 & 3;
    const int wn = w8 >> 2;
    const int l = tid & 31;
    const int b = blockIdx.x >> 5;
    const int y0 = (blockIdx.x & 31) * 2;

    if (tid < 64) *(float*)(smem + BIAS1_OFF + tid * 4) = bias[tid];

    // prefetch B tap0 -> buf0, tap1 -> buf1 (groups 0, 1)
#pragma unroll
    for (int i = 0; i < 4; i++) {
        int idx = tid + i * 256;
        cp16(sb + B1_OFF + idx * 16, g_wtile + idx * 16);
    }
    cp_commit();
#pragma unroll
    for (int i = 0; i < 4; i++) {
        int idx = tid + i * 256;
        cp16(sb + B1_OFF + 16384 + idx * 16, g_wtile + 16384 + idx * 16);
    }
    cp_commit();

    stage_halo<256>(smem, (const uint4*)g_xhi, (const uint4*)g_xlo, b, y0, tid);

    float d[2][4][4];
#pragma unroll
    for (int mt = 0; mt < 2; mt++)
#pragma unroll
        for (int nb = 0; nb < 4; nb++)
#pragma unroll
            for (int j = 0; j < 4; j++) d[mt][nb][j] = 0.f;

    const int lane7 = l & 7;
    const int hi16 = (l >> 4) & 1;
    int ax[2], aly[2];
#pragma unroll
    for (int mt = 0; mt < 2; mt++) {
        int mrow = wm * 32 + mt * 16 + (l & 8) + lane7;
        ax[mt] = mrow & 63;
        aly[mt] = mrow >> 6;
    }
    const int brow = ((l >> 4) & 1) * 8 + lane7;
    const int bcb = (l >> 3) & 1;

#pragma unroll
    for (int tap = 0; tap < 9; tap++) {
        if (tap < 8) cp_wait<1>(); else cp_wait<0>();
        __syncthreads();

        const int dy = tap / 3 - 1;
        const int dx = tap % 3 - 1;
        uint32_t abase[2];
        int akey[2];
#pragma unroll
        for (int mt = 0; mt < 2; mt++) {
            int p = (aly[mt] + dy + 1) * 66 + ax[mt] + dx + 1;
            akey[mt] = p & 7;
            abase[mt] = sb + p * 128;
        }
        const uint32_t btap = sb + B1_OFF + (tap & 1) * 16384;
#pragma unroll
        for (int kb = 0; kb < 4; kb++) {
            uint32_t ah[2][4], al[2][4];
#pragma unroll
            for (int mt = 0; mt < 2; mt++) {
                int chunk = kb * 2 + hi16;
                uint32_t sw = (uint32_t)((chunk ^ akey[mt]) << 4);
                ldsm4(ah[mt], abase[mt] + sw);
                ldsm4(al[mt], abase[mt] + AL_OFF + sw);
            }
#pragma unroll
            for (int nbl = 0; nbl < 2; nbl++) {
                int nbp = wn * 2 + nbl;
                int n = nbp * 16 + brow;
                uint32_t baddr = btap + n * 128 +
                                 (uint32_t)((((kb * 2 + bcb) ^ (n & 7))) << 4);
                uint32_t bh[4], bl[4];
                ldsm4(bh, baddr);
                ldsm4(bl, baddr + 8192);
#pragma unroll
                for (int mt = 0; mt < 2; mt++) {
                    mma16816(d[mt][2 * nbl], ah[mt], bh);
                    mma16816(d[mt][2 * nbl], al[mt], bh);
                    mma16816(d[mt][2 * nbl], ah[mt], bl);
                    mma16816(d[mt][2 * nbl + 1], ah[mt], bh + 2);
                    mma16816(d[mt][2 * nbl + 1], al[mt], bh + 2);
                    mma16816(d[mt][2 * nbl + 1], ah[mt], bl + 2);
                }
            }
        }
        __syncthreads();
        if (tap + 2 <= 8) {
            const uint8_t* src = g_wtile + (tap + 2) * 16384;
            uint32_t dst = sb + B1_OFF + (tap & 1) * 16384;
#pragma unroll
            for (int i = 0; i < 4; i++) {
                int idx = tid + i * 256;
                cp16(dst + idx * 16, src + idx * 16);
            }
            cp_commit();
        }
    }

    // epilogue: bias+relu -> bf16 hi/lo pixel-major
    const int lr = l >> 2;
    const int lc2 = l & 3;
#pragma unroll
    for (int mt = 0; mt < 2; mt++) {
#pragma unroll
        for (int nbl = 0; nbl < 4; nbl++) {
            int nb = wn * 4 + nbl;
            float b0 = *(const float*)(smem + BIAS1_OFF + (nb * 8 + lc2 * 2) * 4);
            float b1 = *(const float*)(smem + BIAS1_OFF + (nb * 8 + lc2 * 2 + 1) * 4);
#pragma unroll
            for (int row = 0; row < 2; row++) {
                int m = wm * 32 + mt * 16 + lr + row * 8;
                float v0 = fmaxf(d[mt][nbl][row * 2 + 0] + b0, 0.f);
                float v1 = fmaxf(d[mt][nbl][row * 2 + 1] + b1, 0.f);
                __nv_bfloat16 h0 = __float2bfloat16(v0);
                __nv_bfloat16 h1 = __float2bfloat16(v1);
                long o = ((long)b * 4096 + y0 * 64 + m) * 32 + nb * 4 + lc2;
                g_x2hi[o] = ((uint32_t)__bfloat16_as_ushort(h1) << 16) |
                            __bfloat16_as_ushort(h0);
                g_x2lo[o] = pack_bf16x2(v0 - __bfloat162float(h0),
                                        v1 - __bfloat162float(h1));
            }
        }
    }
}

// ---------------------------------------------------------------------------
// conv2: block = (b, 2-row strip) -> D[128 pix][16 e]; sigmoid into d_out
// ---------------------------------------------------------------------------
__global__ __launch_bounds__(128) void conv2_mma_kernel(
    const float* __restrict__ bias, float* __restrict__ attn)
{
    extern __shared__ char smem[];
    const uint32_t sb = smem_u32(smem);
    const int tid = threadIdx.x;
    const int w = tid >> 5;
    const int l = tid & 31;
    const int b = blockIdx.x >> 5;
    const int y0 = (blockIdx.x & 31) * 2;

    if (tid < 16) *(float*)(smem + BIAS2_OFF + tid * 4) = bias[tid];

    {
        const uint4* wsrc = (const uint4*)g_wtile2;
        uint4* dst = (uint4*)(smem + B2_OFF);
#pragma unroll
        for (int i = 0; i < 18; i++) dst[tid + i * 128] = wsrc[tid + i * 128];
    }
    stage_halo<128>(smem, (const uint4*)g_x2hi, (const uint4*)g_x2lo, b, y0, tid);
    __syncthreads();

    float d[2][2][4];
#pragma unroll
    for (int mt = 0; mt < 2; mt++)
#pragma unroll
        for (int nb = 0; nb < 2; nb++)
#pragma unroll
            for (int j = 0; j < 4; j++) d[mt][nb][j] = 0.f;

    const int lane7 = l & 7;
    const int hi16 = (l >> 4) & 1;
    int ax[2], aly[2];
#pragma unroll
    for (int mt = 0; mt < 2; mt++) {
        int mrow = w * 32 + mt * 16 + (l & 8) + lane7;
        ax[mt] = mrow & 63;
        aly[mt] = mrow >> 6;
    }
    const int brow = ((l >> 4) & 1) * 8 + lane7;
    const int bcb = (l >> 3) & 1;

#pragma unroll
    for (int tap = 0; tap < 9; tap++) {
        const int dy = tap / 3 - 1;
        const int dx = tap % 3 - 1;
        uint32_t abase[2];
        int akey[2];
#pragma unroll
        for (int mt = 0; mt < 2; mt++) {
            int p = (aly[mt] + dy + 1) * 66 + ax[mt] + dx + 1;
            akey[mt] = p & 7;
            abase[mt] = sb + p * 128;
        }
        const uint32_t btap = sb + B2_OFF + tap * 4096;
#pragma unroll
        for (int kb = 0; kb < 4; kb++) {
            uint32_t ah[2][4], al[2][4];
#pragma unroll
            for (int mt = 0; mt < 2; mt++) {
                int chunk = kb * 2 + hi16;
                uint32_t sw = (uint32_t)((chunk ^ akey[mt]) << 4);
                ldsm4(ah[mt], abase[mt] + sw);
                ldsm4(al[mt], abase[mt] + AL_OFF + sw);
            }
            {
                int n = brow;
                uint32_t baddr = btap + n * 128 +
                                 (uint32_t)((((kb * 2 + bcb) ^ (n & 7))) << 4);
                uint32_t bh[4], bl[4];
                ldsm4(bh, baddr);
                ldsm4(bl, baddr + 2048);
#pragma unroll
                for (int mt = 0; mt < 2; mt++) {
                    mma16816(d[mt][0], ah[mt], bh);
                    mma16816(d[mt][0], al[mt], bh);
                    mma16816(d[mt][0], ah[mt], bl);
                    mma16816(d[mt][1], ah[mt], bh + 2);
                    mma16816(d[mt][1], al[mt], bh + 2);
                    mma16816(d[mt][1], ah[mt], bl + 2);
                }
            }
        }
    }

    const int lr = l >> 2;
    const int lc = (l & 3) * 2;
#pragma unroll
    for (int mt = 0; mt < 2; mt++) {
#pragma unroll
        for (int nb = 0; nb < 2; nb++) {
#pragma unroll
            for (int j = 0; j < 4; j++) {
                int n = nb * 8 + lc + (j & 1);
                int m = w * 32 + mt * 16 + lr + ((j >> 1) * 8);
                float v = d[mt][nb][j] + *(const float*)(smem + BIAS2_OFF + n * 4);
                v = 1.f / (1.f + __expf(-v));
                attn[((long)(b * 16 + n)) * 4096 + y0 * 64 + m] = v;
            }
        }
    }
}

// ---------------------------------------------------------------------------
// fuse: cs-GEMM on HMMA (state bf16 hi/lo x c3_w) + relu-reduction partials.
// block = (b, 128-pixel chunk); 256 threads, warp tile 32x32.
// ---------------------------------------------------------------------------
#define F_AH 0
#define F_AL 16384
#define F_B  32768               /* hi 8K, lo 8K */
#define F_CS 49152               /* 128 x 68 fp32 = 34816 */
#define F_ATT 83968              /* 16 x 128 fp32 = 8192 */
#define FUSE_SMEM 92160

__global__ __launch_bounds__(256) void fuse_kernel(
    const float* __restrict__ attn, const float* __restrict__ c3_b)
{
    extern __shared__ char smem[];
    const uint32_t sb = smem_u32(smem);
    float* cs_s = (float*)(smem + F_CS);
    float* attn_s = (float*)(smem + F_ATT);

    const int tid = threadIdx.x;
    const int w8 = tid >> 5;
    const int wm = w8 & 3;
    const int wn = w8 >> 2;
    const int l = tid & 31;
    const int b = blockIdx.x >> 5;
    const int chunk = blockIdx.x & 31;
    const int pbase = chunk * 128;

    // stage A (128 pixels of state hi/lo, swizzled), B (c3_w tiles), attn
    {
        const uint8_t* srch = (const uint8_t*)g_xhi + ((long)b * 4096 + pbase) * 128;
        const uint8_t* srcl = (const uint8_t*)g_xlo + ((long)b * 4096 + pbase) * 128;
        // 128 pixels x 8 chunks = 1024 16B units; each iteration covers 256
#pragma unroll
        for (int i = 0; i < 4; i++) {
            int idx = tid + i * 256;       // (pp, q)
            int pp = idx >> 3, q = idx & 7;
            uint32_t sw = (uint32_t)(pp * 128 + ((q ^ (pp & 7)) << 4));
            cp16(sb + F_AH + sw, srch + idx * 16);
            cp16(sb + F_AL + sw, srcl + idx * 16);
        }
#pragma unroll
        for (int i = 0; i < 4; i++) {
            int idx = tid + i * 256;
            cp16(sb + F_B + idx * 16, g_wtile3 + idx * 16);
        }
        // attn chunk: 16 e x 128 pp floats = 512 x 16B
#pragma unroll
        for (int i = 0; i < 2; i++) {
            int idx = tid + i * 256;       // 16B unit: (e, pp/4)
            int e = idx >> 5, p4 = idx & 31;
            cp16(sb + F_ATT + idx * 16,
                 attn + ((long)b * 16 + e) * HW + pbase + p4 * 4);
        }
        cp_commit();
        cp_wait<0>();
        __syncthreads();
    }

    // cs-GEMM: D[128 pix][64 o] via 3-term bf16 HMMA
    float d[2][4][4];
#pragma unroll
    for (int mt = 0; mt < 2; mt++)
#pragma unroll
        for (int nb = 0; nb < 4; nb++)
#pragma unroll
            for (int j = 0; j < 4; j++) d[mt][nb][j] = 0.f;

    const int lane7 = l & 7;
    const int hi16 = (l >> 4) & 1;
    const int brow = ((l >> 4) & 1) * 8 + lane7;
    const int bcb = (l >> 3) & 1;

#pragma unroll
    for (int kb = 0; kb < 4; kb++) {
        uint32_t ah[2][4], al[2][4];
#pragma unroll
        for (int mt = 0; mt < 2; mt++) {
            int pp = wm * 32 + mt * 16 + (l & 8) + lane7;
            int chunkq = kb * 2 + hi16;
            uint32_t sw = (uint32_t)(pp * 128 + ((chunkq ^ (pp & 7)) << 4));
            ldsm4(ah[mt], sb + F_AH + sw);
            ldsm4(al[mt], sb + F_AL + sw);
        }
#pragma unroll
        for (int nbl = 0; nbl < 2; nbl++) {
            int nbp = wn * 2 + nbl;
            int n = nbp * 16 + brow;
            uint32_t baddr = sb + F_B + n * 128 +
                             (uint32_t)((((kb * 2 + bcb) ^ (n & 7))) << 4);
            uint32_t bh[4], bl[4];
            ldsm4(bh, baddr);
            ldsm4(bl, baddr + 8192);
#pragma unroll
            for (int mt = 0; mt < 2; mt++) {
                mma16816(d[mt][2 * nbl], ah[mt], bh);
                mma16816(d[mt][2 * nbl], al[mt], bh);
                mma16816(d[mt][2 * nbl], ah[mt], bl);
                mma16816(d[mt][2 * nbl + 1], ah[mt], bh + 2);
                mma16816(d[mt][2 * nbl + 1], al[mt], bh + 2);
                mma16816(d[mt][2 * nbl + 1], ah[mt], bl + 2);
            }
        }
    }

    // write cs fragments to smem [pp][o] pitch 68
    {
        const int lr = l >> 2;
        const int lc = (l & 3) * 2;
#pragma unroll
        for (int mt = 0; mt < 2; mt++) {
#pragma unroll
            for (int nbl = 0; nbl < 4; nbl++) {
                int nb = wn * 4 + nbl;
#pragma unroll
                for (int row = 0; row < 2; row++) {
                    int m = wm * 32 + mt * 16 + lr + row * 8;
                    int n = nb * 8 + lc;
                    float2 v = make_float2(d[mt][nbl][row * 2 + 0],
                                           d[mt][nbl][row * 2 + 1]);
                    *(float2*)(cs_s + m * 68 + n) = v;
                }
            }
        }
    }
    __syncthreads();

    // relu-reduction: thread (e, oq) sums 4 o's over 128 pixels
    {
        const int e = tid >> 4;
        const int oq = tid & 15;
        const float4 bias = ((const float4*)c3_b)[oq];
        float4 acc = make_float4(0.f, 0.f, 0.f, 0.f);
        const float* arow = attn_s + e * 128;
#pragma unroll 4
        for (int pp = 0; pp < 128; pp++) {
            float a = arow[pp];
            float4 cv = *(const float4*)(cs_s + pp * 68 + oq * 4);
            acc.x += fmaxf(fmaf(a, cv.x, bias.x), 0.f);
            acc.y += fmaxf(fmaf(a, cv.y, bias.y), 0.f);
            acc.z += fmaxf(fmaf(a, cv.z, bias.z), 0.f);
            acc.w += fmaxf(fmaf(a, cv.w, bias.w), 0.f);
        }
        float4* po = (float4*)(g_partials + ((long)(b * 32 + chunk)) * 1024 + e * 64 + oq * 4);
        *po = acc;
    }
}

__global__ __launch_bounds__(256) void reduce_kernel(
    const float* __restrict__ c3_b, float* __restrict__ out)
{
    int gid = blockIdx.x * 256 + threadIdx.x;
    int o = gid & 63;
    float sum = 260.f * fmaxf(c3_b[o], 0.f);
    int b = gid >> 10;
    int eo = gid & 1023;
    const float* p = g_partials + (long)b * 32 * 1024 + eo;
#pragma unroll
    for (int c = 0; c < 32; c++) sum += p[c * 1024];
    out[gid] = sum * (1.f / 4356.f);
}

// ---------------------------------------------------------------------------
extern "C" void kernel_launch(void* const* d_in, const int* in_sizes, int n_in,
                              void* d_out, int out_size)
{
    const float* state = (const float*)d_in[0];
    const float* pre_w = (const float*)d_in[1];
    const float* pre_b = (const float*)d_in[2];
    const float* attn_w = (const float*)d_in[3];
    const float* attn_b = (const float*)d_in[4];
    const float* c3_w = (const float*)d_in[5];
    const float* c3_b = (const float*)d_in[6];

    float* out = (float*)d_out;
    float* attn = out + Bn * Ec * Fc;

    cudaFuncSetAttribute(fuse_kernel, cudaFuncAttributeMaxDynamicSharedMemorySize,
                         FUSE_SMEM);
    cudaFuncSetAttribute(conv1_mma_kernel, cudaFuncAttributeMaxDynamicSharedMemorySize,
                         CONV1_SMEM);
    cudaFuncSetAttribute(conv2_mma_kernel, cudaFuncAttributeMaxDynamicSharedMemorySize,
                         CONV2_SMEM);

    // prep: all weights (one kernel) + state to bf16 hi/lo
    wprep_all_kernel<<<98, 256>>>(pre_w, attn_w, c3_w);
    xprep_kernel<<<Bn * 64, 256>>>(state);
    // conv1 on HMMA: B double-buffered via cp.async, 2 CTAs/SM
    conv1_mma_kernel<<<Bn * 32, 256, CONV1_SMEM>>>(pre_b);
    // conv2 on HMMA: x -> attn (sigmoid) straight into d_out
    conv2_mma_kernel<<<Bn * 32, 128, CONV2_SMEM>>>(attn_b, attn);
    // fuse: cs-GEMM on HMMA + relu-reduction partials
    fuse_kernel<<<Bn * 32, 256, FUSE_SMEM>>>(attn, c3_b);
    // final reduce + pad term
    reduce_kernel<<<64, 256>>>(c3_b, out);
}